// round 14
// baseline (speedup 1.0000x reference)
#include <cuda_runtime.h>
#include <cuda_fp16.h>
#include <math.h>
#include <stdint.h>

#define B_ 2
#define T_ 4096
#define E_ 2048
#define E2_ 4096
#define H_ 16
#define KD_ 128
#define HD_ 256
#define CH_ 256
#define NC_ 16
#define NCHUNKS (B_*NC_*H_)   // 512

// ================= scratch =================
__device__ float g_q [B_*T_*E_];
__device__ float g_k [B_*T_*E_];
__device__ float g_v [B_*T_*E2_];
__device__ float g_isc[NCHUNKS*CH_];
__device__ float g_kv [(size_t)NCHUNKS*KD_*HD_];
__device__ float g_kvr[(size_t)NCHUNKS*KD_*HD_];
__device__ float g_csc[NCHUNKS*HD_];
__device__ __half g_innerh[(size_t)NCHUNKS*CH_*HD_];
__device__ __half g_gth[B_*T_*E2_];
__device__ __half g_xh [B_*T_*E_];
__device__ __half g_roh[B_*T_*E2_];
__device__ __half g_wqh[E_*E_];
__device__ __half g_wkh[E_*E_];
__device__ __half g_wvh[(size_t)E2_*E_];
__device__ __half g_wgh[(size_t)E2_*E_];
__device__ __half g_woh[(size_t)E_*E2_];

// ================= helpers =================
__device__ __forceinline__ uint32_t smem_u32(const void* p) {
    uint32_t a;
    asm("{ .reg .u64 t; cvta.to.shared.u64 t, %1; cvt.u32.u64 %0, t; }" : "=r"(a) : "l"(p));
    return a;
}
__device__ __forceinline__ void cp16(uint32_t dst, const void* src) {
    asm volatile("cp.async.cg.shared.global [%0], [%1], 16;" :: "r"(dst), "l"(src));
}
__device__ __forceinline__ void cp_commit() { asm volatile("cp.async.commit_group;"); }
__device__ __forceinline__ void ldm_x4(uint32_t r[4], uint32_t addr) {
    asm volatile("ldmatrix.sync.aligned.m8n8.x4.shared.b16 {%0,%1,%2,%3}, [%4];"
        : "=r"(r[0]), "=r"(r[1]), "=r"(r[2]), "=r"(r[3]) : "r"(addr));
}
__device__ __forceinline__ void mma_f16(float c[4], const uint32_t a[4], const uint32_t b[2]) {
    asm volatile(
        "mma.sync.aligned.m16n8k16.row.col.f32.f16.f16.f32 "
        "{%0,%1,%2,%3}, {%4,%5,%6,%7}, {%8,%9}, {%0,%1,%2,%3};"
        : "+f"(c[0]), "+f"(c[1]), "+f"(c[2]), "+f"(c[3])
        : "r"(a[0]), "r"(a[1]), "r"(a[2]), "r"(a[3]), "r"(b[0]), "r"(b[1]));
}
__device__ __forceinline__ void split2(float a, float b, uint32_t &hi, uint32_t &lo) {
    __half ha = __float2half_rn(a), hb = __float2half_rn(b);
    __half2 H = __halves2half2(ha, hb);
    hi = *reinterpret_cast<uint32_t*>(&H);
    __half2 L = __floats2half2_rn(a - __half2float(ha), b - __half2float(hb));
    lo = *reinterpret_cast<uint32_t*>(&L);
}
__device__ __forceinline__ void split8(const float4& u0, const float4& u1, uint4& hi, uint4& lo) {
    split2(u0.x, u0.y, hi.x, lo.x);
    split2(u0.z, u0.w, hi.y, lo.y);
    split2(u1.x, u1.y, hi.z, lo.z);
    split2(u1.z, u1.w, hi.w, lo.w);
}

// ================= fused f32 -> f16 converter =================
#define N4_X  (B_*T_*E_/4)
#define N4_WQ (E_*E_/4)
#define N4_WV (E2_*E_/4)
#define F4_0  N4_X
#define F4_1  (F4_0 + N4_WQ)
#define F4_2  (F4_1 + N4_WQ)
#define F4_3  (F4_2 + N4_WV)
#define F4_4  (F4_3 + N4_WV)
#define F4_TOT (F4_4 + N4_WV)

__global__ void f2h_all(const float* __restrict__ x,
                        const float* __restrict__ Wq, const float* __restrict__ Wk,
                        const float* __restrict__ Wv, const float* __restrict__ Wg,
                        const float* __restrict__ Wo)
{
    int i = blockIdx.x * blockDim.x + threadIdx.x;
    if (i >= F4_TOT) return;
    const float* src; __half* dst; int off;
    if (i < F4_0)      { src = x;  dst = g_xh;  off = i; }
    else if (i < F4_1) { src = Wq; dst = g_wqh; off = i - F4_0; }
    else if (i < F4_2) { src = Wk; dst = g_wkh; off = i - F4_1; }
    else if (i < F4_3) { src = Wv; dst = g_wvh; off = i - F4_2; }
    else if (i < F4_4) { src = Wg; dst = g_wgh; off = i - F4_3; }
    else               { src = Wo; dst = g_woh; off = i - F4_4; }
    float4 v = *(const float4*)(src + (size_t)off * 4);
    __half2 h[2];
    h[0] = __floats2half2_rn(v.x, v.y);
    h[1] = __floats2half2_rn(v.z, v.w);
    *(uint2*)(dst + (size_t)off * 4) = *(uint2*)h;
}

// ===== fp16 tensor-core GEMM core: 3-stage pipeline =====
#define BKH 64
#define TILEA 18432
#define STGB  36864
#define GEMMH_SMEM (3*STGB)

template<int ACT>
__device__ __forceinline__ void gemm_h_body(
    const __half* __restrict__ A, const __half* __restrict__ W,
    const float* __restrict__ bias, void* __restrict__ Cout,
    int K, int Ncols, float scale,
    const float* __restrict__ sn, const float* __restrict__ cs, char* smh)
{
    const int tid = threadIdx.x;
    const int wid = tid >> 5, lane = tid & 31;
    const int wm = wid & 1, wn = wid >> 1;
    const int g = lane >> 2, q = lane & 3;
    const int bx = blockIdx.x, by = blockIdx.y;

    const __half* Ab = A + (size_t)(by * 128) * K;
    const __half* Wb = W + (size_t)(bx * 128) * K;
    const uint32_t sb = smem_u32(smh);

    const int lr  = tid >> 1;
    const int lcu = (tid & 1) * 4;
    const int lrow8 = (lane & 7) + ((lane >> 3) & 1) * 8;
    const int koffB = (lane >> 4) * 16;
    const uint32_t ldoff = (uint32_t)(lr * 144 + lcu * 16);

    float acc[4][4][4] = {};
    const int NS = K / BKH;

    #pragma unroll
    for (int s = 0; s < 2; s++) {
        const uint32_t stg = sb + (uint32_t)s * STGB;
        const __half* As = Ab + (size_t)lr * K + s * BKH + lcu * 8;
        const __half* Ws = Wb + (size_t)lr * K + s * BKH + lcu * 8;
        #pragma unroll
        for (int i = 0; i < 4; i++) {
            cp16(stg + ldoff + i * 16, As + i * 8);
            cp16(stg + TILEA + ldoff + i * 16, Ws + i * 8);
        }
        cp_commit();
    }

    for (int s = 0; s < NS; s++) {
        asm volatile("cp.async.wait_group 1;");
        __syncthreads();
        if (s + 2 < NS) {
            const uint32_t stg = sb + (uint32_t)((s + 2) % 3) * STGB;
            const __half* As = Ab + (size_t)lr * K + (s + 2) * BKH + lcu * 8;
            const __half* Ws = Wb + (size_t)lr * K + (s + 2) * BKH + lcu * 8;
            #pragma unroll
            for (int i = 0; i < 4; i++) {
                cp16(stg + ldoff + i * 16, As + i * 8);
                cp16(stg + TILEA + ldoff + i * 16, Ws + i * 8);
            }
        }
        cp_commit();

        const uint32_t stg = sb + (uint32_t)(s % 3) * STGB;
        const uint32_t a_base = stg + (uint32_t)((wm * 64 + lrow8) * 144 + koffB);
        const uint32_t b_base = stg + TILEA + (uint32_t)((wn * 32 + lrow8) * 144 + koffB);
        #pragma unroll
        for (int ks = 0; ks < 4; ks++) {
            const uint32_t kc2 = ks * 32;
            uint32_t af[4][4];
            #pragma unroll
            for (int mf = 0; mf < 4; mf++) ldm_x4(af[mf], a_base + mf * 16 * 144 + kc2);
            uint32_t bf[4][2];
            #pragma unroll
            for (int nf2 = 0; nf2 < 2; nf2++) {
                uint32_t t4[4];
                ldm_x4(t4, b_base + nf2 * 16 * 144 + kc2);
                bf[2*nf2  ][0] = t4[0]; bf[2*nf2  ][1] = t4[2];
                bf[2*nf2+1][0] = t4[1]; bf[2*nf2+1][1] = t4[3];
            }
            #pragma unroll
            for (int mf = 0; mf < 4; mf++)
                #pragma unroll
                for (int nf = 0; nf < 4; nf++)
                    mma_f16(acc[mf][nf], af[mf], bf[nf]);
        }
    }

    #pragma unroll
    for (int mf = 0; mf < 4; mf++) {
        #pragma unroll
        for (int nf = 0; nf < 4; nf++) {
            const int row = by * 128 + wm * 64 + mf * 16 + g;
            const int col = bx * 128 + wn * 32 + nf * 8 + q * 2;
            const float b0 = bias[col], b1 = bias[col + 1];
            float o00 = (acc[mf][nf][0] + b0) * scale;
            float o01 = (acc[mf][nf][1] + b1) * scale;
            float o10 = (acc[mf][nf][2] + b0) * scale;
            float o11 = (acc[mf][nf][3] + b1) * scale;
            if (ACT == 2) {
                const int d = col & (KD_ - 1);
                const int t0 = row & (T_ - 1);
                const int t1 = t0 + 8;
                float c0 = cs[t0*KD_ + d], c1 = cs[t0*KD_ + d + 1];
                float s0 = sn[t0*KD_ + d], s1 = sn[t0*KD_ + d + 1];
                float r0 = o00 * c0 - o01 * s0;
                float r1 = o01 * c1 + o00 * s1;
                o00 = r0; o01 = r1;
                c0 = cs[t1*KD_ + d]; c1 = cs[t1*KD_ + d + 1];
                s0 = sn[t1*KD_ + d]; s1 = sn[t1*KD_ + d + 1];
                r0 = o10 * c0 - o11 * s0;
                r1 = o11 * c1 + o10 * s1;
                o10 = r0; o11 = r1;
            }
            if (ACT == 1) {
                __half* C = (__half*)Cout;
                float s00 = o00 / (1.f + expf(-o00));
                float s01 = o01 / (1.f + expf(-o01));
                float s10 = o10 / (1.f + expf(-o10));
                float s11 = o11 / (1.f + expf(-o11));
                __half2 h0 = __floats2half2_rn(s00, s01);
                __half2 h1 = __floats2half2_rn(s10, s11);
                *(uint32_t*)(C + (size_t)row * Ncols + col) = *(uint32_t*)&h0;
                *(uint32_t*)(C + (size_t)(row + 8) * Ncols + col) = *(uint32_t*)&h1;
            } else {
                float* C = (float*)Cout;
                *(float2*)(C + (size_t)row * Ncols + col) = make_float2(o00, o01);
                *(float2*)(C + (size_t)(row + 8) * Ncols + col) = make_float2(o10, o11);
            }
        }
    }
}

__global__ void __launch_bounds__(256)
gemm_qk(const __half* __restrict__ A,
        const __half* __restrict__ Wq, const float* __restrict__ bq,
        const __half* __restrict__ Wk, const float* __restrict__ bk,
        float kscale,
        const float* __restrict__ sn, const float* __restrict__ cs)
{
    extern __shared__ __align__(128) char smh[];
    if (blockIdx.z == 0)
        gemm_h_body<2>(A, Wq, bq, g_q, E_, E_, 1.f, sn, cs, smh);
    else
        gemm_h_body<2>(A, Wk, bk, g_k, E_, E_, kscale, sn, cs, smh);
}

__global__ void __launch_bounds__(256)
gemm_vg(const __half* __restrict__ A,
        const __half* __restrict__ Wv, const float* __restrict__ bv,
        const __half* __restrict__ Wg, const float* __restrict__ bg)
{
    extern __shared__ __align__(128) char smh[];
    if (blockIdx.z == 0)
        gemm_h_body<0>(A, Wv, bv, g_v, E_, E2_, 1.f, nullptr, nullptr, smh);
    else
        gemm_h_body<1>(A, Wg, bg, g_gth, E_, E2_, 1.f, nullptr, nullptr, smh);
}

__global__ void __launch_bounds__(256)
gemm_h(const __half* __restrict__ A, const __half* __restrict__ W,
       const float* __restrict__ bias, float* __restrict__ C,
       int K, int Ncols, float scale)
{
    extern __shared__ __align__(128) char smh[];
    gemm_h_body<0>(A, W, bias, C, K, Ncols, scale, nullptr, nullptr, smh);
}

// ===== fused qk -> mask -> isc -> inner (split-fp16, 512 threads) =====
#define P1   272
#define AQH_ 0
#define AQL_ 34816
#define BKHo 69632
#define BKLo 139264
#define PQ   528
#define QKHo 0
#define QKLo 67584
#define PV   144
#define VHo  135168
#define VLo  172032
#define ISCP 208896          // 128 rows * 8 warps * 4B = 4096
#define ISCS 212992
#define QKI_SMEM 213504

__global__ void __launch_bounds__(512, 1)
qki_kernel(const float* __restrict__ mask)
{
    extern __shared__ __align__(128) char sm[];
    const uint32_t sb = smem_u32(sm);
    const int tid = threadIdx.x;
    const int wid = tid >> 5, lane = tid & 31;
    const int wm = wid & 1, wn = wid >> 1;          // 2(M) x 8(N)
    const int g = lane >> 2, q = lane & 3;
    const int z = blockIdx.x, chunk = z >> 1, hf = z & 1;
    const int b = chunk / (NC_*H_);
    const int n = (chunk / H_) % NC_;
    const int h = chunk % H_;
    const int row0 = hf * 128;

    const int lrow8 = (lane & 7) + ((lane >> 3) & 1) * 8;
    const int koffB = (lane >> 4) * 16;

    const float* qsrc = g_q + ((size_t)(b*T_ + n*CH_ + row0)) * E_ + h*KD_;
    const float* ksrc = g_k + ((size_t)(b*T_ + n*CH_)) * E_ + h*KD_;
    {
        const int r_ = tid >> 4, c_ = (tid & 15) * 8;   // 32 rows/pass
        #pragma unroll
        for (int p = 0; p < 4; p++) {
            int r = p * 32 + r_;
            float4 u0 = *(const float4*)(qsrc + (size_t)r * E_ + c_);
            float4 u1 = *(const float4*)(qsrc + (size_t)r * E_ + c_ + 4);
            uint4 hi, lo; split8(u0, u1, hi, lo);
            *(uint4*)(sm + AQH_ + r * P1 + c_ * 2) = hi;
            *(uint4*)(sm + AQL_ + r * P1 + c_ * 2) = lo;
        }
        #pragma unroll
        for (int p = 0; p < 8; p++) {
            int r = p * 32 + r_;
            float4 u0 = *(const float4*)(ksrc + (size_t)r * E_ + c_);
            float4 u1 = *(const float4*)(ksrc + (size_t)r * E_ + c_ + 4);
            uint4 hi, lo; split8(u0, u1, hi, lo);
            *(uint4*)(sm + BKHo + r * P1 + c_ * 2) = hi;
            *(uint4*)(sm + BKLo + r * P1 + c_ * 2) = lo;
        }
    }
    __syncthreads();

    float acc[4][4][4] = {};

    // ---- phase 1: qk (3 split passes) ----
    {
        const uint32_t ao[3] = {AQH_, AQH_, AQL_};
        const uint32_t bo[3] = {BKHo, BKLo, BKHo};
        #pragma unroll
        for (int ps = 0; ps < 3; ps++) {
            const uint32_t a_base = sb + ao[ps] + (uint32_t)((wm*64 + lrow8) * P1 + koffB);
            const uint32_t b_base = sb + bo[ps] + (uint32_t)((wn*32 + lrow8) * P1 + koffB);
            #pragma unroll
            for (int ks = 0; ks < 8; ks++) {
                const uint32_t kb = ks * 32;
                uint32_t af[4][4];
                #pragma unroll
                for (int mf = 0; mf < 4; mf++) ldm_x4(af[mf], a_base + mf * 16 * P1 + kb);
                uint32_t bf[4][2];
                #pragma unroll
                for (int nf2 = 0; nf2 < 2; nf2++) {
                    uint32_t t4[4];
                    ldm_x4(t4, b_base + nf2 * 16 * P1 + kb);
                    bf[2*nf2  ][0] = t4[0]; bf[2*nf2  ][1] = t4[2];
                    bf[2*nf2+1][0] = t4[1]; bf[2*nf2+1][1] = t4[3];
                }
                #pragma unroll
                for (int mf = 0; mf < 4; mf++)
                    #pragma unroll
                    for (int nf = 0; nf < 4; nf++)
                        mma_f16(acc[mf][nf], af[mf], bf[nf]);
            }
        }
    }
    __syncthreads();

    // ---- mask, row sums, split-store qkm ----
    {
        float psl[4] = {0,0,0,0}, psh[4] = {0,0,0,0};
        const float* mbase = mask + (size_t)h * (CH_*CH_) + (size_t)row0 * CH_;
        #pragma unroll
        for (int mf = 0; mf < 4; mf++) {
            const int r0 = wm*64 + mf*16 + g, r1 = r0 + 8;
            const float* m0 = mbase + (size_t)r0 * CH_;
            const float* m1 = mbase + (size_t)r1 * CH_;
            #pragma unroll
            for (int nf = 0; nf < 4; nf++) {
                const int c0 = wn*32 + nf*8 + q*2;
                float v00 = acc[mf][nf][0] * m0[c0];
                float v01 = acc[mf][nf][1] * m0[c0+1];
                float v10 = acc[mf][nf][2] * m1[c0];
                float v11 = acc[mf][nf][3] * m1[c0+1];
                psl[mf] += fabsf(v00) + fabsf(v01);
                psh[mf] += fabsf(v10) + fabsf(v11);
                uint32_t h0, l0, h1, l1;
                split2(v00, v01, h0, l0);
                split2(v10, v11, h1, l1);
                *(uint32_t*)(sm + QKHo + r0 * PQ + c0 * 2) = h0;
                *(uint32_t*)(sm + QKLo + r0 * PQ + c0 * 2) = l0;
                *(uint32_t*)(sm + QKHo + r1 * PQ + c0 * 2) = h1;
                *(uint32_t*)(sm + QKLo + r1 * PQ + c0 * 2) = l1;
            }
        }
        float* iscp = (float*)(sm + ISCP);
        #pragma unroll
        for (int mf = 0; mf < 4; mf++) {
            float pl = psl[mf], ph = psh[mf];
            pl += __shfl_xor_sync(0xffffffffu, pl, 1);
            pl += __shfl_xor_sync(0xffffffffu, pl, 2);
            ph += __shfl_xor_sync(0xffffffffu, ph, 1);
            ph += __shfl_xor_sync(0xffffffffu, ph, 2);
            if (q == 0) {
                iscp[(wm*64 + mf*16 + g) * 8 + wn] = pl;
                iscp[(wm*64 + mf*16 + g + 8) * 8 + wn] = ph;
            }
        }
    }
    __syncthreads();
    if (tid < 128) {
        const float* ip = (const float*)(sm + ISCP) + tid * 8;
        float s = ip[0] + ip[1] + ip[2] + ip[3] + ip[4] + ip[5] + ip[6] + ip[7];
        g_isc[chunk*CH_ + row0 + tid] = s;
        ((float*)(sm + ISCS))[tid] = fmaxf(s, 1.f);
    }

    #pragma unroll
    for (int mf = 0; mf < 4; mf++)
        #pragma unroll
        for (int nf = 0; nf < 4; nf++)
            #pragma unroll
            for (int e = 0; e < 4; e++) acc[mf][nf][e] = 0.f;

    const float* vsrc = g_v + ((size_t)(b*T_ + n*CH_)) * E2_ + h*HD_;
    for (int sl = 0; sl < 4; sl++) {
        __syncthreads();
        {
            const int d2 = (tid >> 6) << 1;        // 0..14 even
            const int c_ = (tid & 63) * 4;
            #pragma unroll
            for (int p = 0; p < 4; p++) {
                int dl = p * 16 + d2;
                int d = sl * 64 + dl;
                float4 ua = *(const float4*)(vsrc + (size_t)d * E2_ + c_);
                float4 ub = *(const float4*)(vsrc + (size_t)(d + 1) * E2_ + c_);
                const float fa[4] = {ua.x, ua.y, ua.z, ua.w};
                const float fb[4] = {ub.x, ub.y, ub.z, ub.w};
                #pragma unroll
                for (int j = 0; j < 4; j++) {
                    uint32_t hi, lo;
                    split2(fa[j], fb[j], hi, lo);
                    *(uint32_t*)(sm + VHo + (c_ + j) * PV + dl * 2) = hi;
                    *(uint32_t*)(sm + VLo + (c_ + j) * PV + dl * 2) = lo;
                }
            }
        }
        __syncthreads();
        const uint32_t ao[3] = {QKHo, QKHo, QKLo};
        const uint32_t bo[3] = {VHo, VLo, VHo};
        #pragma unroll
        for (int ps = 0; ps < 3; ps++) {
            const uint32_t a_base = sb + ao[ps] + (uint32_t)((wm*64 + lrow8) * PQ + sl * 128 + koffB);
            const uint32_t b_base = sb + bo[ps] + (uint32_t)((wn*32 + lrow8) * PV + koffB);
            #pragma unroll
            for (int ks = 0; ks < 4; ks++) {
                const uint32_t kb = ks * 32;
                uint32_t af[4][4];
                #pragma unroll
                for (int mf = 0; mf < 4; mf++) ldm_x4(af[mf], a_base + mf * 16 * PQ + kb);
                uint32_t bf[4][2];
                #pragma unroll
                for (int nf2 = 0; nf2 < 2; nf2++) {
                    uint32_t t4[4];
                    ldm_x4(t4, b_base + nf2 * 16 * PV + kb);
                    bf[2*nf2  ][0] = t4[0]; bf[2*nf2  ][1] = t4[2];
                    bf[2*nf2+1][0] = t4[1]; bf[2*nf2+1][1] = t4[3];
                }
                #pragma unroll
                for (int mf = 0; mf < 4; mf++)
                    #pragma unroll
                    for (int nf = 0; nf < 4; nf++)
                        mma_f16(acc[mf][nf], af[mf], bf[nf]);
            }
        }
    }

    {
        const float* iscs = (const float*)(sm + ISCS);
        __half* op = g_innerh + (size_t)chunk * (CH_*HD_) + (size_t)row0 * HD_;
        #pragma unroll
        for (int mf = 0; mf < 4; mf++) {
            const int r0 = wm*64 + mf*16 + g, r1 = r0 + 8;
            const float inv0 = 1.f / iscs[r0];
            const float inv1 = 1.f / iscs[r1];
            #pragma unroll
            for (int nf = 0; nf < 4; nf++) {
                const int c0 = wn*32 + nf*8 + q*2;
                __half2 h0 = __floats2half2_rn(acc[mf][nf][0] * inv0, acc[mf][nf][1] * inv0);
                __half2 h1 = __floats2half2_rn(acc[mf][nf][2] * inv1, acc[mf][nf][3] * inv1);
                *(uint32_t*)(op + (size_t)r0 * HD_ + c0) = *(uint32_t*)&h0;
                *(uint32_t*)(op + (size_t)r1 * HD_ + c0) = *(uint32_t*)&h1;
            }
        }
    }
}

// ===== kv = (w*k)^T @ v  (split-fp16 mma) =====
#define KT_H 0
#define KT_L 18432
#define KVT_H 36864
#define KVT_L 73728
#define KV_SMEM 110592

__global__ void __launch_bounds__(256, 1)
kv_mma(const float* __restrict__ mask)
{
    extern __shared__ __align__(128) char sm[];
    const uint32_t sb = smem_u32(sm);
    const int tid = threadIdx.x;
    const int wid = tid >> 5, lane = tid & 31;
    const int wm = wid & 1, wn = wid >> 1;
    const int g = lane >> 2, q = lane & 3;
    const int chunk = blockIdx.x;
    const int b = chunk / (NC_*H_);
    const int n = (chunk / H_) % NC_;
    const int h = chunk % H_;
    const int lrow8 = (lane & 7) + ((lane >> 3) & 1) * 8;
    const int koffB = (lane >> 4) * 16;

    const float* ksrc = g_k + ((size_t)(b*T_ + n*CH_)) * E_ + h*KD_;
    const float* vsrc = g_v + ((size_t)(b*T_ + n*CH_)) * E2_ + h*HD_;
    const float* wrow = mask + (size_t)h * (CH_*CH_) + (size_t)(CH_-1) * CH_;

    float acc[4][8][4] = {};

    for (int sl = 0; sl < 4; sl++) {
        __syncthreads();
        {
            const int cp = (tid >> 3) << 1;
            const int kb_ = (tid & 7) * 16;
            const int c = sl * 64 + cp;
            const float w0 = wrow[c], w1 = wrow[c + 1];
            const float* s0 = ksrc + (size_t)c * E_;
            const float* s1 = ksrc + (size_t)(c + 1) * E_;
            #pragma unroll
            for (int p = 0; p < 4; p++) {
                const int kd = kb_ + p * 4;
                float4 u0 = *(const float4*)(s0 + kd);
                float4 u1 = *(const float4*)(s1 + kd);
                const float f0[4] = {u0.x * w0, u0.y * w0, u0.z * w0, u0.w * w0};
                const float f1[4] = {u1.x * w1, u1.y * w1, u1.z * w1, u1.w * w1};
                #pragma unroll
                for (int j = 0; j < 4; j++) {
                    uint32_t hi, lo;
                    split2(f0[j], f1[j], hi, lo);
                    *(uint32_t*)(sm + KT_H + (kd + j) * 144 + cp * 2) = hi;
                    *(uint32_t*)(sm + KT_L + (kd + j) * 144 + cp * 2) = lo;
                }
            }
        }
        {
            const int d2 = (tid >> 6) << 1;
            const int c_ = (tid & 63) * 4;
            #pragma unroll
            for (int p = 0; p < 8; p++) {
                int dl = p * 8 + d2;
                int c = sl * 64 + dl;
                float4 ua = *(const float4*)(vsrc + (size_t)c * E2_ + c_);
                float4 ub = *(const float4*)(vsrc + (size_t)(c + 1) * E2_ + c_);
                const float fa[4] = {ua.x, ua.y, ua.z, ua.w};
                const float fb[4] = {ub.x, ub.y, ub.z, ub.w};
                #pragma unroll
                for (int j = 0; j < 4; j++) {
                    uint32_t hi, lo;
                    split2(fa[j], fb[j], hi, lo);
                    *(uint32_t*)(sm + KVT_H + (c_ + j) * 144 + dl * 2) = hi;
                    *(uint32_t*)(sm + KVT_L + (c_ + j) * 144 + dl * 2) = lo;
                }
            }
        }
        __syncthreads();
        const uint32_t ao[3] = {KT_H, KT_H, KT_L};
        const uint32_t bo[3] = {KVT_H, KVT_L, KVT_H};
        #pragma unroll
        for (int ps = 0; ps < 3; ps++) {
            const uint32_t a_base = sb + ao[ps] + (uint32_t)((wm*64 + lrow8) * 144 + koffB);
            const uint32_t b_base = sb + bo[ps] + (uint32_t)((wn*64 + lrow8) * 144 + koffB);
            #pragma unroll
            for (int ks = 0; ks < 4; ks++) {
                const uint32_t kb = ks * 32;
                uint32_t af[4][4];
                #pragma unroll
                for (int mf = 0; mf < 4; mf++) ldm_x4(af[mf], a_base + mf * 16 * 144 + kb);
                uint32_t bf[8][2];
                #pragma unroll
                for (int nf2 = 0; nf2 < 4; nf2++) {
                    uint32_t t4[4];
                    ldm_x4(t4, b_base + nf2 * 16 * 144 + kb);
                    bf[2*nf2  ][0] = t4[0]; bf[2*nf2  ][1] = t4[2];
                    bf[2*nf2+1][0] = t4[1]; bf[2*nf2+1][1] = t4[3];
                }
                #pragma unroll
                for (int mf = 0; mf < 4; mf++)
                    #pragma unroll
                    for (int nf = 0; nf < 8; nf++)
                        mma_f16(acc[mf][nf], af[mf], bf[nf]);
            }
        }
    }

    float* op = g_kv + (size_t)chunk * (KD_*HD_);
    #pragma unroll
    for (int mf = 0; mf < 4; mf++) {
        const int r0 = wm*64 + mf*16 + g, r1 = r0 + 8;
        #pragma unroll
        for (int nf = 0; nf < 8; nf++) {
            const int c0 = wn*64 + nf*8 + q*2;
            *(float2*)(op + (size_t)r0 * HD_ + c0) = make_float2(acc[mf][nf][0], acc[mf][nf][1]);
            *(float2*)(op + (size_t)r1 * HD_ + c0) = make_float2(acc[mf][nf][2], acc[mf][nf][3]);
        }
    }
}

// ---------------- cross-chunk scan ----------------
__global__ __launch_bounds__(256)
void scan_kernel(const float* __restrict__ cdec)
{
    const int vb = blockIdx.x & 15;
    const int bh = blockIdx.x >> 4;
    const int b = bh / H_, h = bh % H_;
    const int v0 = vb * 16;
    const int tid = threadIdx.x;
    const int v = tid & 15;
    const int kg = tid >> 4;
    float s[8] = {0,0,0,0,0,0,0,0};
    __shared__ float sc[16];
    __shared__ float red[256];
    if (tid < 16) sc[tid] = 1.f;
    __syncthreads();
    const float cd = cdec[h];
    for (int n = 0; n < NC_; n++) {
        const int chunk = (b*NC_ + n)*H_ + h;
        const size_t zo = (size_t)chunk * (KD_*HD_);
        float invsc = 1.f / sc[v];
        #pragma unroll
        for (int i = 0; i < 8; i++)
            g_kvr[zo + (size_t)(kg*8+i)*HD_ + v0 + v] = s[i] * invsc;
        if (tid < 16) g_csc[chunk*HD_ + v0 + tid] = sc[tid];
        float p = 0.f;
        #pragma unroll
        for (int i = 0; i < 8; i++) {
            s[i] = s[i]*cd + g_kv[zo + (size_t)(kg*8+i)*HD_ + v0 + v];
            p += fabsf(s[i]);
        }
        red[tid] = p;
        __syncthreads();
        if (tid < 16) {
            float sum = 0.f;
            #pragma unroll
            for (int j = 0; j < 16; j++) sum += red[j*16 + tid];
            sc[tid] = fmaxf(sum, 1.f);
        }
        __syncthreads();
    }
}

// ===== cross = (qr*idec) @ kv_rec + combine + LN + silu gate (split-fp16) =====
#define CA_H  0
#define CA_L  34816
#define CB_H  69632
#define CB_L  106496
#define CPART 143360
#define CRCSC 147456
#define CRISC 148480
#define CROSS_SMEM 148992

__global__ void __launch_bounds__(256, 1)
cross_mma(const float* __restrict__ idec)
{
    extern __shared__ __align__(128) char sm[];
    const uint32_t sb = smem_u32(sm);
    const int tid = threadIdx.x;
    const int wid = tid >> 5, lane = tid & 31;
    const int wm = wid & 1, wn = wid >> 1;
    const int g = lane >> 2, q = lane & 3;
    const int z = blockIdx.x, chunk = z >> 1, hf = z & 1;
    const int b = chunk / (NC_*H_);
    const int n = (chunk / H_) % NC_;
    const int h = chunk % H_;
    const int row0 = hf * 128;
    const int lrow8 = (lane & 7) + ((lane >> 3) & 1) * 8;
    const int koffB = (lane >> 4) * 16;

    {
        float c = g_csc[chunk*HD_ + tid];
        ((float*)(sm + CRCSC))[tid] = 1.f / c;
        if (tid < 128) {
            float s = g_isc[chunk*CH_ + row0 + tid];
            ((float*)(sm + CRISC))[tid] = 1.f / fmaxf(s, 1.f);
        }
    }
    {
        const float* qsrc = g_q + ((size_t)(b*T_ + n*CH_ + row0)) * E_ + h*KD_;
        const int r_ = tid >> 4, c_ = (tid & 15) * 8;
        #pragma unroll
        for (int p = 0; p < 8; p++) {
            int r = p * 16 + r_;
            float aw = idec[h*CH_ + row0 + r];
            float4 u0 = *(const float4*)(qsrc + (size_t)r * E_ + c_);
            float4 u1 = *(const float4*)(qsrc + (size_t)r * E_ + c_ + 4);
            u0.x *= aw; u0.y *= aw; u0.z *= aw; u0.w *= aw;
            u1.x *= aw; u1.y *= aw; u1.z *= aw; u1.w *= aw;
            uint4 hi, lo; split8(u0, u1, hi, lo);
            *(uint4*)(sm + CA_H + r * 272 + c_ * 2) = hi;
            *(uint4*)(sm + CA_L + r * 272 + c_ * 2) = lo;
        }
    }

    float acc[4][8][4] = {};
    const float* kvrsrc = g_kvr + (size_t)chunk * (KD_*HD_);

    for (int sl = 0; sl < 2; sl++) {
        __syncthreads();
        {
            const int d2 = (tid >> 6) << 1;
            const int c_ = (tid & 63) * 4;
            #pragma unroll
            for (int p = 0; p < 8; p++) {
                int dl = p * 8 + d2;
                int kd = sl * 64 + dl;
                float4 ua = *(const float4*)(kvrsrc + (size_t)kd * HD_ + c_);
                float4 ub = *(const float4*)(kvrsrc + (size_t)(kd + 1) * HD_ + c_);
                const float fa[4] = {ua.x, ua.y, ua.z, ua.w};
                const float fb[4] = {ub.x, ub.y, ub.z, ub.w};
                #pragma unroll
                for (int j = 0; j < 4; j++) {
                    uint32_t hi, lo;
                    split2(fa[j], fb[j], hi, lo);
                    *(uint32_t*)(sm + CB_H + (c_ + j) * 144 + dl * 2) = hi;
                    *(uint32_t*)(sm + CB_L + (c_ + j) * 144 + dl * 2) = lo;
                }
            }
        }
        __syncthreads();
        const uint32_t ao[3] = {CA_H, CA_H, CA_L};
        const uint32_t bo[3] = {CB_H, CB_L, CB_H};
        #pragma unroll
        for (int ps = 0; ps < 3; ps++) {
            const uint32_t a_base = sb + ao[ps] + (uint32_t)((wm*64 + lrow8) * 272 + sl * 128 + koffB);
            const uint32_t b_base = sb + bo[ps] + (uint32_t)((wn*64 + lrow8) * 144 + koffB);
            #pragma unroll
            for (int ks = 0; ks < 4; ks++) {
                const uint32_t kb = ks * 32;
                uint32_t af[4][4];
                #pragma unroll
                for (int mf = 0; mf < 4; mf++) ldm_x4(af[mf], a_base + mf * 16 * 272 + kb);
                uint32_t bf[8][2];
                #pragma unroll
                for (int nf2 = 0; nf2 < 4; nf2++) {
                    uint32_t t4[4];
                    ldm_x4(t4, b_base + nf2 * 16 * 144 + kb);
                    bf[2*nf2  ][0] = t4[0]; bf[2*nf2  ][1] = t4[2];
                    bf[2*nf2+1][0] = t4[1]; bf[2*nf2+1][1] = t4[3];
                }
                #pragma unroll
                for (int mf = 0; mf < 4; mf++)
                    #pragma unroll
                    for (int nf = 0; nf < 8; nf++)
                        mma_f16(acc[mf][nf], af[mf], bf[nf]);
            }
        }
    }

    const __half* innp = g_innerh + (size_t)chunk * (CH_*HD_) + (size_t)row0 * HD_;
    const float* rcsc = (const float*)(sm + CRCSC);
    const float* risc = (const float*)(sm + CRISC);
    float* part = (float*)(sm + CPART);

    #pragma unroll
    for (int mf = 0; mf < 4; mf++) {
        const int r0 = wm*64 + mf*16 + g, r1 = r0 + 8;
        const float i0 = risc[r0], i1 = risc[r1];
        float s0 = 0.f, q0 = 0.f, s1 = 0.f, q1 = 0.f;
        #pragma unroll
        for (int nf = 0; nf < 8; nf++) {
            const int c0 = wn*64 + nf*8 + q*2;
            const float rc0 = rcsc[c0], rc1 = rcsc[c0+1];
            float2 in0 = __half22float2(*(const __half2*)(innp + (size_t)r0 * HD_ + c0));
            float2 in1 = __half22float2(*(const __half2*)(innp + (size_t)r1 * HD_ + c0));
            float o00 = in0.x * rc0 + acc[mf][nf][0] * i0;
            float o01 = in0.y * rc1 + acc[mf][nf][1] * i0;
            float o10 = in1.x * rc0 + acc[mf][nf][2] * i1;
            float o11 = in1.y * rc1 + acc[mf][nf][3] * i1;
            acc[mf][nf][0] = o00; acc[mf][nf][1] = o01;
            acc[mf][nf][2] = o10; acc[mf][nf][3] = o11;
            s0 += o00 + o01; q0 += o00*o00 + o01*o01;
            s1 += o10 + o11; q1 += o10*o10 + o11*o11;
        }
        s0 += __shfl_xor_sync(0xffffffffu, s0, 1); s0 += __shfl_xor_sync(0xffffffffu, s0, 2);
        q0 += __shfl_xor_sync(0xffffffffu, q0, 1); q0 += __shfl_xor_sync(0xffffffffu, q0, 2);
        s1 += __shfl_xor_sync(0xffffffffu, s1, 1); s1 += __shfl_xor_sync(0xffffffffu, s1, 2);
        q1 += __shfl_xor_sync(0xffffffffu, q1, 1); q1 += __shfl_xor_sync(0xffffffffu, q1, 2);
        if (q == 0) {
            part[(r0*4 + wn)*2    ] = s0;
            part[(r0*4 + wn)*2 + 1] = q0;
            part[(r1*4 + wn)*2    ] = s1;
            part[(r1*4 + wn)*2 + 1] = q1;
        }
    }
    __syncthreads();

    const __half* gp = g_gth + ((size_t)(b*T_ + n*CH_ + row0)) * E2_ + h*HD_;
    __half* rop      = g_roh + ((size_t)(b*T_ + n*CH_ + row0)) * E2_ + h*HD_;
    #pragma unroll
    for (int mf = 0; mf < 4; mf++) {
        const int r0 = wm*64 + mf*16 + g, r1 = r0 + 8;
        float rs0 = part[(r0*4+0)*2] + part[(r0*4+1)*2] + part[(r0*4+2)*2] + part[(r0*4+3)*2];
        float rq0 = part[(r0*4+0)*2+1] + part[(r0*4+1)*2+1] + part[(r0*4+2)*2+1] + part[(r0*4+3)*2+1];
        float rs1 = part[(r1*4+0)*2] + part[(r1*4+1)*2] + part[(r1*4+2)*2] + part[(r1*4+3)*2];
        float rq1 = part[(r1*4+0)*2+1] + part[(r1*4+1)*2+1] + part[(r1*4+2)*2+1] + part[(r1*4+3)*2+1];
        const float mean0 = rs0 * (1.f/HD_);
        const float mean1 = rs1 * (1.f/HD_);
        const float rstd0 = rsqrtf(rq0 * (1.f/HD_) - mean0*mean0 + 1e-5f);
        const float rstd1 = rsqrtf(rq1 * (1.f/HD_) - mean1*mean1 + 1e-5f);
        #pragma unroll
        for (int nf = 0; nf < 8; nf++) {
            const int c0 = wn*64 + nf*8 + q*2;
            float2 gs0 = __half22float2(*(const __half2*)(gp + (size_t)r0 * E2_ + c0));
            float2 gs1 = __half22float2(*(const __half2*)(gp + (size_t)r1 * E2_ + c0));
            float o00 = gs0.x * (acc[mf][nf][0] - mean0) * rstd0;
            float o01 = gs0.y * (acc[mf][nf][1] - mean0) * rstd0;
            float o10 = gs1.x * (acc[mf][nf][2] - mean1) * rstd1;
            float o11 = gs1.y * (acc[mf][nf][3] - mean1) * rstd1;
            __half2 h0 = __floats2half2_rn(o00, o01);
            __half2 h1 = __floats2half2_rn(o10, o11);
            *(uint32_t*)(rop + (size_t)r0 * E2_ + c0) = *(uint32_t*)&h0;
            *(uint32_t*)(rop + (size_t)r1 * E2_ + c0) = *(uint32_t*)&h1;
        }
    }
}

// ================= launch =================
extern "C" void kernel_launch(void* const* d_in, const int* in_sizes, int n_in,
                              void* d_out, int out_size)
{
    const float* x    = (const float*)d_in[0];
    const float* sn   = (const float*)d_in[1];
    const float* cs   = (const float*)d_in[2];
    const float* mask = (const float*)d_in[3];
    const float* cdec = (const float*)d_in[4];
    const float* idec = (const float*)d_in[5];
    const float* Wq = (const float*)d_in[6];
    const float* bq = (const float*)d_in[7];
    const float* Wk = (const float*)d_in[8];
    const float* bk = (const float*)d_in[9];
    const float* Wv = (const float*)d_in[10];
    const float* bv = (const float*)d_in[11];
    const float* Wg = (const float*)d_in[12];
    const float* bg = (const float*)d_in[13];
    const float* Wo = (const float*)d_in[14];
    const float* bo = (const float*)d_in[15];
    float* out = (float*)d_out;

    __half *xh, *roh, *wqh, *wkh, *wvh, *wgh, *woh;
    cudaGetSymbolAddress((void**)&xh,  g_xh);
    cudaGetSymbolAddress((void**)&roh, g_roh);
    cudaGetSymbolAddress((void**)&wqh, g_wqh);
    cudaGetSymbolAddress((void**)&wkh, g_wkh);
    cudaGetSymbolAddress((void**)&wvh, g_wvh);
    cudaGetSymbolAddress((void**)&wgh, g_wgh);
    cudaGetSymbolAddress((void**)&woh, g_woh);

    cudaFuncSetAttribute(gemm_h, cudaFuncAttributeMaxDynamicSharedMemorySize, GEMMH_SMEM);
    cudaFuncSetAttribute(gemm_qk, cudaFuncAttributeMaxDynamicSharedMemorySize, GEMMH_SMEM);
    cudaFuncSetAttribute(gemm_vg, cudaFuncAttributeMaxDynamicSharedMemorySize, GEMMH_SMEM);
    cudaFuncSetAttribute(qki_kernel, cudaFuncAttributeMaxDynamicSharedMemorySize, QKI_SMEM);
    cudaFuncSetAttribute(kv_mma, cudaFuncAttributeMaxDynamicSharedMemorySize, KV_SMEM);
    cudaFuncSetAttribute(cross_mma, cudaFuncAttributeMaxDynamicSharedMemorySize, CROSS_SMEM);

    const int M = B_*T_;
    const float kscale = 1.0f / sqrtf((float)KD_);

    f2h_all<<<(F4_TOT + 255)/256, 256>>>(x, Wq, Wk, Wv, Wg, Wo);

    gemm_qk<<<dim3(E_/128,  M/128, 2), 256, GEMMH_SMEM>>>(xh, wqh, bq, wkh, bk, kscale, sn, cs);
    gemm_vg<<<dim3(E2_/128, M/128, 2), 256, GEMMH_SMEM>>>(xh, wvh, bv, wgh, bg);
    qki_kernel<<<2*NCHUNKS, 512, QKI_SMEM>>>(mask);
    kv_mma    <<<NCHUNKS,   256, KV_SMEM>>>(mask);
    scan_kernel<<<B_*H_*(HD_/16), 256>>>(cdec);
    cross_mma <<<2*NCHUNKS, 256, CROSS_SMEM>>>(idec);
    gemm_h<<<dim3(E_/128, M/128), 256, GEMMH_SMEM>>>(roh, woh, bo, out, E2_, E_, 1.f);
}

// round 15
// speedup vs baseline: 1.0195x; 1.0195x over previous
#include <cuda_runtime.h>
#include <cuda_fp16.h>
#include <math.h>
#include <stdint.h>

#define B_ 2
#define T_ 4096
#define E_ 2048
#define E2_ 4096
#define H_ 16
#define KD_ 128
#define HD_ 256
#define CH_ 256
#define NC_ 16
#define NCHUNKS (B_*NC_*H_)   // 512

// ================= scratch =================
__device__ float g_q [B_*T_*E_];
__device__ float g_k [B_*T_*E_];
__device__ float g_v [B_*T_*E2_];
__device__ float g_isc[NCHUNKS*CH_];
__device__ float g_kv [(size_t)NCHUNKS*KD_*HD_];
__device__ float g_kvr[(size_t)NCHUNKS*KD_*HD_];
__device__ float g_csc[NCHUNKS*HD_];
__device__ __half g_innerh[(size_t)NCHUNKS*CH_*HD_];
__device__ __half g_gth[B_*T_*E2_];
__device__ __half g_xh [B_*T_*E_];
__device__ __half g_roh[B_*T_*E2_];
__device__ __half g_wqh[E_*E_];
__device__ __half g_wkh[E_*E_];
__device__ __half g_wvh[(size_t)E2_*E_];
__device__ __half g_wgh[(size_t)E2_*E_];
__device__ __half g_woh[(size_t)E_*E2_];

// ================= helpers =================
__device__ __forceinline__ uint32_t smem_u32(const void* p) {
    uint32_t a;
    asm("{ .reg .u64 t; cvta.to.shared.u64 t, %1; cvt.u32.u64 %0, t; }" : "=r"(a) : "l"(p));
    return a;
}
__device__ __forceinline__ void cp16(uint32_t dst, const void* src) {
    asm volatile("cp.async.cg.shared.global [%0], [%1], 16;" :: "r"(dst), "l"(src));
}
__device__ __forceinline__ void cp_commit() { asm volatile("cp.async.commit_group;"); }
__device__ __forceinline__ void ldm_x4(uint32_t r[4], uint32_t addr) {
    asm volatile("ldmatrix.sync.aligned.m8n8.x4.shared.b16 {%0,%1,%2,%3}, [%4];"
        : "=r"(r[0]), "=r"(r[1]), "=r"(r[2]), "=r"(r[3]) : "r"(addr));
}
__device__ __forceinline__ void mma_f16(float c[4], const uint32_t a[4], const uint32_t b[2]) {
    asm volatile(
        "mma.sync.aligned.m16n8k16.row.col.f32.f16.f16.f32 "
        "{%0,%1,%2,%3}, {%4,%5,%6,%7}, {%8,%9}, {%0,%1,%2,%3};"
        : "+f"(c[0]), "+f"(c[1]), "+f"(c[2]), "+f"(c[3])
        : "r"(a[0]), "r"(a[1]), "r"(a[2]), "r"(a[3]), "r"(b[0]), "r"(b[1]));
}
__device__ __forceinline__ void split2(float a, float b, uint32_t &hi, uint32_t &lo) {
    __half ha = __float2half_rn(a), hb = __float2half_rn(b);
    __half2 H = __halves2half2(ha, hb);
    hi = *reinterpret_cast<uint32_t*>(&H);
    __half2 L = __floats2half2_rn(a - __half2float(ha), b - __half2float(hb));
    lo = *reinterpret_cast<uint32_t*>(&L);
}
__device__ __forceinline__ void split8(const float4& u0, const float4& u1, uint4& hi, uint4& lo) {
    split2(u0.x, u0.y, hi.x, lo.x);
    split2(u0.z, u0.w, hi.y, lo.y);
    split2(u1.x, u1.y, hi.z, lo.z);
    split2(u1.z, u1.w, hi.w, lo.w);
}
// unpack a B ldmatrix.x4 result into two n8 fragments
__device__ __forceinline__ void unpack_b(const uint32_t t4[4], uint32_t b0[2], uint32_t b1[2]) {
    b0[0] = t4[0]; b0[1] = t4[2];
    b1[0] = t4[1]; b1[1] = t4[3];
}

// ================= fused f32 -> f16 converter =================
#define N4_X  (B_*T_*E_/4)
#define N4_WQ (E_*E_/4)
#define N4_WV (E2_*E_/4)
#define F4_0  N4_X
#define F4_1  (F4_0 + N4_WQ)
#define F4_2  (F4_1 + N4_WQ)
#define F4_3  (F4_2 + N4_WV)
#define F4_4  (F4_3 + N4_WV)
#define F4_TOT (F4_4 + N4_WV)

__global__ void f2h_all(const float* __restrict__ x,
                        const float* __restrict__ Wq, const float* __restrict__ Wk,
                        const float* __restrict__ Wv, const float* __restrict__ Wg,
                        const float* __restrict__ Wo)
{
    int i = blockIdx.x * blockDim.x + threadIdx.x;
    if (i >= F4_TOT) return;
    const float* src; __half* dst; int off;
    if (i < F4_0)      { src = x;  dst = g_xh;  off = i; }
    else if (i < F4_1) { src = Wq; dst = g_wqh; off = i - F4_0; }
    else if (i < F4_2) { src = Wk; dst = g_wkh; off = i - F4_1; }
    else if (i < F4_3) { src = Wv; dst = g_wvh; off = i - F4_2; }
    else if (i < F4_4) { src = Wg; dst = g_wgh; off = i - F4_3; }
    else               { src = Wo; dst = g_woh; off = i - F4_4; }
    float4 v = *(const float4*)(src + (size_t)off * 4);
    __half2 h[2];
    h[0] = __floats2half2_rn(v.x, v.y);
    h[1] = __floats2half2_rn(v.z, v.w);
    *(uint2*)(dst + (size_t)off * 4) = *(uint2*)h;
}

// ===== fp16 tensor-core GEMM core: 3-stage pipeline =====
#define BKH 64
#define TILEA 18432
#define STGB  36864
#define GEMMH_SMEM (3*STGB)

template<int ACT>
__device__ __forceinline__ void gemm_h_body(
    const __half* __restrict__ A, const __half* __restrict__ W,
    const float* __restrict__ bias, void* __restrict__ Cout,
    int K, int Ncols, float scale,
    const float* __restrict__ sn, const float* __restrict__ cs, char* smh)
{
    const int tid = threadIdx.x;
    const int wid = tid >> 5, lane = tid & 31;
    const int wm = wid & 1, wn = wid >> 1;
    const int g = lane >> 2, q = lane & 3;
    const int bx = blockIdx.x, by = blockIdx.y;

    const __half* Ab = A + (size_t)(by * 128) * K;
    const __half* Wb = W + (size_t)(bx * 128) * K;
    const uint32_t sb = smem_u32(smh);

    const int lr  = tid >> 1;
    const int lcu = (tid & 1) * 4;
    const int lrow8 = (lane & 7) + ((lane >> 3) & 1) * 8;
    const int koffB = (lane >> 4) * 16;
    const uint32_t ldoff = (uint32_t)(lr * 144 + lcu * 16);

    float acc[4][4][4] = {};
    const int NS = K / BKH;

    #pragma unroll
    for (int s = 0; s < 2; s++) {
        const uint32_t stg = sb + (uint32_t)s * STGB;
        const __half* As = Ab + (size_t)lr * K + s * BKH + lcu * 8;
        const __half* Ws = Wb + (size_t)lr * K + s * BKH + lcu * 8;
        #pragma unroll
        for (int i = 0; i < 4; i++) {
            cp16(stg + ldoff + i * 16, As + i * 8);
            cp16(stg + TILEA + ldoff + i * 16, Ws + i * 8);
        }
        cp_commit();
    }

    for (int s = 0; s < NS; s++) {
        asm volatile("cp.async.wait_group 1;");
        __syncthreads();
        if (s + 2 < NS) {
            const uint32_t stg = sb + (uint32_t)((s + 2) % 3) * STGB;
            const __half* As = Ab + (size_t)lr * K + (s + 2) * BKH + lcu * 8;
            const __half* Ws = Wb + (size_t)lr * K + (s + 2) * BKH + lcu * 8;
            #pragma unroll
            for (int i = 0; i < 4; i++) {
                cp16(stg + ldoff + i * 16, As + i * 8);
                cp16(stg + TILEA + ldoff + i * 16, Ws + i * 8);
            }
        }
        cp_commit();

        const uint32_t stg = sb + (uint32_t)(s % 3) * STGB;
        const uint32_t a_base = stg + (uint32_t)((wm * 64 + lrow8) * 144 + koffB);
        const uint32_t b_base = stg + TILEA + (uint32_t)((wn * 32 + lrow8) * 144 + koffB);
        #pragma unroll
        for (int ks = 0; ks < 4; ks++) {
            const uint32_t kc2 = ks * 32;
            uint32_t af[4][4];
            #pragma unroll
            for (int mf = 0; mf < 4; mf++) ldm_x4(af[mf], a_base + mf * 16 * 144 + kc2);
            uint32_t bf[4][2];
            #pragma unroll
            for (int nf2 = 0; nf2 < 2; nf2++) {
                uint32_t t4[4];
                ldm_x4(t4, b_base + nf2 * 16 * 144 + kc2);
                unpack_b(t4, bf[2*nf2], bf[2*nf2+1]);
            }
            #pragma unroll
            for (int mf = 0; mf < 4; mf++)
                #pragma unroll
                for (int nf = 0; nf < 4; nf++)
                    mma_f16(acc[mf][nf], af[mf], bf[nf]);
        }
    }

    #pragma unroll
    for (int mf = 0; mf < 4; mf++) {
        #pragma unroll
        for (int nf = 0; nf < 4; nf++) {
            const int row = by * 128 + wm * 64 + mf * 16 + g;
            const int col = bx * 128 + wn * 32 + nf * 8 + q * 2;
            const float b0 = bias[col], b1 = bias[col + 1];
            float o00 = (acc[mf][nf][0] + b0) * scale;
            float o01 = (acc[mf][nf][1] + b1) * scale;
            float o10 = (acc[mf][nf][2] + b0) * scale;
            float o11 = (acc[mf][nf][3] + b1) * scale;
            if (ACT == 2) {
                const int d = col & (KD_ - 1);
                const int t0 = row & (T_ - 1);
                const int t1 = t0 + 8;
                float c0 = cs[t0*KD_ + d], c1 = cs[t0*KD_ + d + 1];
                float s0 = sn[t0*KD_ + d], s1 = sn[t0*KD_ + d + 1];
                float r0 = o00 * c0 - o01 * s0;
                float r1 = o01 * c1 + o00 * s1;
                o00 = r0; o01 = r1;
                c0 = cs[t1*KD_ + d]; c1 = cs[t1*KD_ + d + 1];
                s0 = sn[t1*KD_ + d]; s1 = sn[t1*KD_ + d + 1];
                r0 = o10 * c0 - o11 * s0;
                r1 = o11 * c1 + o10 * s1;
                o10 = r0; o11 = r1;
            }
            if (ACT == 1) {
                __half* C = (__half*)Cout;
                float s00 = o00 / (1.f + expf(-o00));
                float s01 = o01 / (1.f + expf(-o01));
                float s10 = o10 / (1.f + expf(-o10));
                float s11 = o11 / (1.f + expf(-o11));
                __half2 h0 = __floats2half2_rn(s00, s01);
                __half2 h1 = __floats2half2_rn(s10, s11);
                *(uint32_t*)(C + (size_t)row * Ncols + col) = *(uint32_t*)&h0;
                *(uint32_t*)(C + (size_t)(row + 8) * Ncols + col) = *(uint32_t*)&h1;
            } else {
                float* C = (float*)Cout;
                *(float2*)(C + (size_t)row * Ncols + col) = make_float2(o00, o01);
                *(float2*)(C + (size_t)(row + 8) * Ncols + col) = make_float2(o10, o11);
            }
        }
    }
}

__global__ void __launch_bounds__(256)
gemm_qk(const __half* __restrict__ A,
        const __half* __restrict__ Wq, const float* __restrict__ bq,
        const __half* __restrict__ Wk, const float* __restrict__ bk,
        float kscale,
        const float* __restrict__ sn, const float* __restrict__ cs)
{
    extern __shared__ __align__(128) char smh[];
    if (blockIdx.z == 0)
        gemm_h_body<2>(A, Wq, bq, g_q, E_, E_, 1.f, sn, cs, smh);
    else
        gemm_h_body<2>(A, Wk, bk, g_k, E_, E_, kscale, sn, cs, smh);
}

__global__ void __launch_bounds__(256)
gemm_vg(const __half* __restrict__ A,
        const __half* __restrict__ Wv, const float* __restrict__ bv,
        const __half* __restrict__ Wg, const float* __restrict__ bg)
{
    extern __shared__ __align__(128) char smh[];
    if (blockIdx.z == 0)
        gemm_h_body<0>(A, Wv, bv, g_v, E_, E2_, 1.f, nullptr, nullptr, smh);
    else
        gemm_h_body<1>(A, Wg, bg, g_gth, E_, E2_, 1.f, nullptr, nullptr, smh);
}

__global__ void __launch_bounds__(256)
gemm_h(const __half* __restrict__ A, const __half* __restrict__ W,
       const float* __restrict__ bias, float* __restrict__ C,
       int K, int Ncols, float scale)
{
    extern __shared__ __align__(128) char smh[];
    gemm_h_body<0>(A, W, bias, C, K, Ncols, scale, nullptr, nullptr, smh);
}

// ===== fused qk -> mask -> isc -> inner (split-fp16, merged passes) =====
#define P1   272
#define AQH_ 0
#define AQL_ 34816
#define BKHo 69632
#define BKLo 139264
#define PQ   528
#define QKHo 0
#define QKLo 67584
#define PV   144
#define VHo  135168
#define VLo  172032
#define ISCP 208896
#define ISCS 210944
#define QKI_SMEM 211456

__global__ void __launch_bounds__(256, 1)
qki_kernel(const float* __restrict__ mask)
{
    extern __shared__ __align__(128) char sm[];
    const uint32_t sb = smem_u32(sm);
    const int tid = threadIdx.x;
    const int wid = tid >> 5, lane = tid & 31;
    const int wm = wid & 1, wn = wid >> 1;
    const int g = lane >> 2, q = lane & 3;
    const int z = blockIdx.x, chunk = z >> 1, hf = z & 1;
    const int b = chunk / (NC_*H_);
    const int n = (chunk / H_) % NC_;
    const int h = chunk % H_;
    const int row0 = hf * 128;

    const int lrow8 = (lane & 7) + ((lane >> 3) & 1) * 8;
    const int koffB = (lane >> 4) * 16;

    const float* qsrc = g_q + ((size_t)(b*T_ + n*CH_ + row0)) * E_ + h*KD_;
    const float* ksrc = g_k + ((size_t)(b*T_ + n*CH_)) * E_ + h*KD_;
    {
        const int r_ = tid >> 4, c_ = (tid & 15) * 8;
        #pragma unroll
        for (int p = 0; p < 8; p++) {
            int r = p * 16 + r_;
            float4 u0 = *(const float4*)(qsrc + (size_t)r * E_ + c_);
            float4 u1 = *(const float4*)(qsrc + (size_t)r * E_ + c_ + 4);
            uint4 hi, lo; split8(u0, u1, hi, lo);
            *(uint4*)(sm + AQH_ + r * P1 + c_ * 2) = hi;
            *(uint4*)(sm + AQL_ + r * P1 + c_ * 2) = lo;
        }
        #pragma unroll
        for (int p = 0; p < 16; p++) {
            int r = p * 16 + r_;
            float4 u0 = *(const float4*)(ksrc + (size_t)r * E_ + c_);
            float4 u1 = *(const float4*)(ksrc + (size_t)r * E_ + c_ + 4);
            uint4 hi, lo; split8(u0, u1, hi, lo);
            *(uint4*)(sm + BKHo + r * P1 + c_ * 2) = hi;
            *(uint4*)(sm + BKLo + r * P1 + c_ * 2) = lo;
        }
    }
    __syncthreads();

    float acc[4][8][4] = {};

    // ---- phase 1: qk, merged 3-pass (load aH,aL,bH,bL once per k-step) ----
    {
        const uint32_t aH = sb + AQH_ + (uint32_t)((wm*64 + lrow8) * P1 + koffB);
        const uint32_t aL = sb + AQL_ + (uint32_t)((wm*64 + lrow8) * P1 + koffB);
        const uint32_t bH = sb + BKHo + (uint32_t)((wn*64 + lrow8) * P1 + koffB);
        const uint32_t bL = sb + BKLo + (uint32_t)((wn*64 + lrow8) * P1 + koffB);
        #pragma unroll
        for (int ks = 0; ks < 8; ks++) {
            const uint32_t kb = ks * 32;
            uint32_t afH[4][4], afL[4][4];
            #pragma unroll
            for (int mf = 0; mf < 4; mf++) {
                ldm_x4(afH[mf], aH + mf * 16 * P1 + kb);
                ldm_x4(afL[mf], aL + mf * 16 * P1 + kb);
            }
            uint32_t bfH[8][2], bfL[8][2];
            #pragma unroll
            for (int nf2 = 0; nf2 < 4; nf2++) {
                uint32_t t4[4];
                ldm_x4(t4, bH + nf2 * 16 * P1 + kb);
                unpack_b(t4, bfH[2*nf2], bfH[2*nf2+1]);
                ldm_x4(t4, bL + nf2 * 16 * P1 + kb);
                unpack_b(t4, bfL[2*nf2], bfL[2*nf2+1]);
            }
            #pragma unroll
            for (int mf = 0; mf < 4; mf++)
                #pragma unroll
                for (int nf = 0; nf < 8; nf++) {
                    mma_f16(acc[mf][nf], afH[mf], bfH[nf]);
                    mma_f16(acc[mf][nf], afH[mf], bfL[nf]);
                    mma_f16(acc[mf][nf], afL[mf], bfH[nf]);
                }
        }
    }
    __syncthreads();

    {
        float psl[4] = {0,0,0,0}, psh[4] = {0,0,0,0};
        const float* mbase = mask + (size_t)h * (CH_*CH_) + (size_t)row0 * CH_;
        #pragma unroll
        for (int mf = 0; mf < 4; mf++) {
            const int r0 = wm*64 + mf*16 + g, r1 = r0 + 8;
            const float* m0 = mbase + (size_t)r0 * CH_;
            const float* m1 = mbase + (size_t)r1 * CH_;
            #pragma unroll
            for (int nf = 0; nf < 8; nf++) {
                const int c0 = wn*64 + nf*8 + q*2;
                float v00 = acc[mf][nf][0] * m0[c0];
                float v01 = acc[mf][nf][1] * m0[c0+1];
                float v10 = acc[mf][nf][2] * m1[c0];
                float v11 = acc[mf][nf][3] * m1[c0+1];
                psl[mf] += fabsf(v00) + fabsf(v01);
                psh[mf] += fabsf(v10) + fabsf(v11);
                uint32_t h0, l0, h1, l1;
                split2(v00, v01, h0, l0);
                split2(v10, v11, h1, l1);
                *(uint32_t*)(sm + QKHo + r0 * PQ + c0 * 2) = h0;
                *(uint32_t*)(sm + QKLo + r0 * PQ + c0 * 2) = l0;
                *(uint32_t*)(sm + QKHo + r1 * PQ + c0 * 2) = h1;
                *(uint32_t*)(sm + QKLo + r1 * PQ + c0 * 2) = l1;
            }
        }
        float* iscp = (float*)(sm + ISCP);
        #pragma unroll
        for (int mf = 0; mf < 4; mf++) {
            float pl = psl[mf], ph = psh[mf];
            pl += __shfl_xor_sync(0xffffffffu, pl, 1);
            pl += __shfl_xor_sync(0xffffffffu, pl, 2);
            ph += __shfl_xor_sync(0xffffffffu, ph, 1);
            ph += __shfl_xor_sync(0xffffffffu, ph, 2);
            if (q == 0) {
                iscp[(wm*64 + mf*16 + g) * 4 + wn] = pl;
                iscp[(wm*64 + mf*16 + g + 8) * 4 + wn] = ph;
            }
        }
    }
    __syncthreads();
    if (tid < 128) {
        const float* ip = (const float*)(sm + ISCP) + tid * 4;
        float s = ip[0] + ip[1] + ip[2] + ip[3];
        g_isc[chunk*CH_ + row0 + tid] = s;
        ((float*)(sm + ISCS))[tid] = fmaxf(s, 1.f);
    }

    #pragma unroll
    for (int mf = 0; mf < 4; mf++)
        #pragma unroll
        for (int nf = 0; nf < 8; nf++)
            #pragma unroll
            for (int e = 0; e < 4; e++) acc[mf][nf][e] = 0.f;

    const float* vsrc = g_v + ((size_t)(b*T_ + n*CH_)) * E2_ + h*HD_;
    for (int sl = 0; sl < 4; sl++) {
        __syncthreads();
        {
            const int d2 = (tid >> 6) << 1;
            const int c_ = (tid & 63) * 4;
            #pragma unroll
            for (int p = 0; p < 8; p++) {
                int dl = p * 8 + d2;
                int d = sl * 64 + dl;
                float4 ua = *(const float4*)(vsrc + (size_t)d * E2_ + c_);
                float4 ub = *(const float4*)(vsrc + (size_t)(d + 1) * E2_ + c_);
                const float fa[4] = {ua.x, ua.y, ua.z, ua.w};
                const float fb[4] = {ub.x, ub.y, ub.z, ub.w};
                #pragma unroll
                for (int j = 0; j < 4; j++) {
                    uint32_t hi, lo;
                    split2(fa[j], fb[j], hi, lo);
                    *(uint32_t*)(sm + VHo + (c_ + j) * PV + dl * 2) = hi;
                    *(uint32_t*)(sm + VLo + (c_ + j) * PV + dl * 2) = lo;
                }
            }
        }
        __syncthreads();
        // merged 3-pass inner mma
        const uint32_t aH = sb + QKHo + (uint32_t)((wm*64 + lrow8) * PQ + sl * 128 + koffB);
        const uint32_t aL = sb + QKLo + (uint32_t)((wm*64 + lrow8) * PQ + sl * 128 + koffB);
        const uint32_t bH = sb + VHo + (uint32_t)((wn*64 + lrow8) * PV + koffB);
        const uint32_t bL = sb + VLo + (uint32_t)((wn*64 + lrow8) * PV + koffB);
        #pragma unroll
        for (int ks = 0; ks < 4; ks++) {
            const uint32_t kb = ks * 32;
            uint32_t afH[4][4], afL[4][4];
            #pragma unroll
            for (int mf = 0; mf < 4; mf++) {
                ldm_x4(afH[mf], aH + mf * 16 * PQ + kb);
                ldm_x4(afL[mf], aL + mf * 16 * PQ + kb);
            }
            uint32_t bfH[8][2], bfL[8][2];
            #pragma unroll
            for (int nf2 = 0; nf2 < 4; nf2++) {
                uint32_t t4[4];
                ldm_x4(t4, bH + nf2 * 16 * PV + kb);
                unpack_b(t4, bfH[2*nf2], bfH[2*nf2+1]);
                ldm_x4(t4, bL + nf2 * 16 * PV + kb);
                unpack_b(t4, bfL[2*nf2], bfL[2*nf2+1]);
            }
            #pragma unroll
            for (int mf = 0; mf < 4; mf++)
                #pragma unroll
                for (int nf = 0; nf < 8; nf++) {
                    mma_f16(acc[mf][nf], afH[mf], bfH[nf]);
                    mma_f16(acc[mf][nf], afH[mf], bfL[nf]);
                    mma_f16(acc[mf][nf], afL[mf], bfH[nf]);
                }
        }
    }

    {
        const float* iscs = (const float*)(sm + ISCS);
        __half* op = g_innerh + (size_t)chunk * (CH_*HD_) + (size_t)row0 * HD_;
        #pragma unroll
        for (int mf = 0; mf < 4; mf++) {
            const int r0 = wm*64 + mf*16 + g, r1 = r0 + 8;
            const float inv0 = 1.f / iscs[r0];
            const float inv1 = 1.f / iscs[r1];
            #pragma unroll
            for (int nf = 0; nf < 8; nf++) {
                const int c0 = wn*64 + nf*8 + q*2;
                __half2 h0 = __floats2half2_rn(acc[mf][nf][0] * inv0, acc[mf][nf][1] * inv0);
                __half2 h1 = __floats2half2_rn(acc[mf][nf][2] * inv1, acc[mf][nf][3] * inv1);
                *(uint32_t*)(op + (size_t)r0 * HD_ + c0) = *(uint32_t*)&h0;
                *(uint32_t*)(op + (size_t)r1 * HD_ + c0) = *(uint32_t*)&h1;
            }
        }
    }
}

// ===== kv = (w*k)^T @ v  (split-fp16, merged passes) =====
#define KT_H 0
#define KT_L 18432
#define KVT_H 36864
#define KVT_L 73728
#define KV_SMEM 110592

__global__ void __launch_bounds__(256, 1)
kv_mma(const float* __restrict__ mask)
{
    extern __shared__ __align__(128) char sm[];
    const uint32_t sb = smem_u32(sm);
    const int tid = threadIdx.x;
    const int wid = tid >> 5, lane = tid & 31;
    const int wm = wid & 1, wn = wid >> 1;
    const int g = lane >> 2, q = lane & 3;
    const int chunk = blockIdx.x;
    const int b = chunk / (NC_*H_);
    const int n = (chunk / H_) % NC_;
    const int h = chunk % H_;
    const int lrow8 = (lane & 7) + ((lane >> 3) & 1) * 8;
    const int koffB = (lane >> 4) * 16;

    const float* ksrc = g_k + ((size_t)(b*T_ + n*CH_)) * E_ + h*KD_;
    const float* vsrc = g_v + ((size_t)(b*T_ + n*CH_)) * E2_ + h*HD_;
    const float* wrow = mask + (size_t)h * (CH_*CH_) + (size_t)(CH_-1) * CH_;

    float acc[4][8][4] = {};

    for (int sl = 0; sl < 4; sl++) {
        __syncthreads();
        {
            const int cp = (tid >> 3) << 1;
            const int kb_ = (tid & 7) * 16;
            const int c = sl * 64 + cp;
            const float w0 = wrow[c], w1 = wrow[c + 1];
            const float* s0 = ksrc + (size_t)c * E_;
            const float* s1 = ksrc + (size_t)(c + 1) * E_;
            #pragma unroll
            for (int p = 0; p < 4; p++) {
                const int kd = kb_ + p * 4;
                float4 u0 = *(const float4*)(s0 + kd);
                float4 u1 = *(const float4*)(s1 + kd);
                const float f0[4] = {u0.x * w0, u0.y * w0, u0.z * w0, u0.w * w0};
                const float f1[4] = {u1.x * w1, u1.y * w1, u1.z * w1, u1.w * w1};
                #pragma unroll
                for (int j = 0; j < 4; j++) {
                    uint32_t hi, lo;
                    split2(f0[j], f1[j], hi, lo);
                    *(uint32_t*)(sm + KT_H + (kd + j) * 144 + cp * 2) = hi;
                    *(uint32_t*)(sm + KT_L + (kd + j) * 144 + cp * 2) = lo;
                }
            }
        }
        {
            const int d2 = (tid >> 6) << 1;
            const int c_ = (tid & 63) * 4;
            #pragma unroll
            for (int p = 0; p < 8; p++) {
                int dl = p * 8 + d2;
                int c = sl * 64 + dl;
                float4 ua = *(const float4*)(vsrc + (size_t)c * E2_ + c_);
                float4 ub = *(const float4*)(vsrc + (size_t)(c + 1) * E2_ + c_);
                const float fa[4] = {ua.x, ua.y, ua.z, ua.w};
                const float fb[4] = {ub.x, ub.y, ub.z, ub.w};
                #pragma unroll
                for (int j = 0; j < 4; j++) {
                    uint32_t hi, lo;
                    split2(fa[j], fb[j], hi, lo);
                    *(uint32_t*)(sm + KVT_H + (c_ + j) * 144 + dl * 2) = hi;
                    *(uint32_t*)(sm + KVT_L + (c_ + j) * 144 + dl * 2) = lo;
                }
            }
        }
        __syncthreads();
        const uint32_t aH = sb + KT_H + (uint32_t)((wm*64 + lrow8) * 144 + koffB);
        const uint32_t aL = sb + KT_L + (uint32_t)((wm*64 + lrow8) * 144 + koffB);
        const uint32_t bH = sb + KVT_H + (uint32_t)((wn*64 + lrow8) * 144 + koffB);
        const uint32_t bL = sb + KVT_L + (uint32_t)((wn*64 + lrow8) * 144 + koffB);
        #pragma unroll
        for (int ks = 0; ks < 4; ks++) {
            const uint32_t kb = ks * 32;
            uint32_t afH[4][4], afL[4][4];
            #pragma unroll
            for (int mf = 0; mf < 4; mf++) {
                ldm_x4(afH[mf], aH + mf * 16 * 144 + kb);
                ldm_x4(afL[mf], aL + mf * 16 * 144 + kb);
            }
            uint32_t bfH[8][2], bfL[8][2];
            #pragma unroll
            for (int nf2 = 0; nf2 < 4; nf2++) {
                uint32_t t4[4];
                ldm_x4(t4, bH + nf2 * 16 * 144 + kb);
                unpack_b(t4, bfH[2*nf2], bfH[2*nf2+1]);
                ldm_x4(t4, bL + nf2 * 16 * 144 + kb);
                unpack_b(t4, bfL[2*nf2], bfL[2*nf2+1]);
            }
            #pragma unroll
            for (int mf = 0; mf < 4; mf++)
                #pragma unroll
                for (int nf = 0; nf < 8; nf++) {
                    mma_f16(acc[mf][nf], afH[mf], bfH[nf]);
                    mma_f16(acc[mf][nf], afH[mf], bfL[nf]);
                    mma_f16(acc[mf][nf], afL[mf], bfH[nf]);
                }
        }
    }

    float* op = g_kv + (size_t)chunk * (KD_*HD_);
    #pragma unroll
    for (int mf = 0; mf < 4; mf++) {
        const int r0 = wm*64 + mf*16 + g, r1 = r0 + 8;
        #pragma unroll
        for (int nf = 0; nf < 8; nf++) {
            const int c0 = wn*64 + nf*8 + q*2;
            *(float2*)(op + (size_t)r0 * HD_ + c0) = make_float2(acc[mf][nf][0], acc[mf][nf][1]);
            *(float2*)(op + (size_t)r1 * HD_ + c0) = make_float2(acc[mf][nf][2], acc[mf][nf][3]);
        }
    }
}

// ---------------- cross-chunk scan ----------------
__global__ __launch_bounds__(256)
void scan_kernel(const float* __restrict__ cdec)
{
    const int vb = blockIdx.x & 15;
    const int bh = blockIdx.x >> 4;
    const int b = bh / H_, h = bh % H_;
    const int v0 = vb * 16;
    const int tid = threadIdx.x;
    const int v = tid & 15;
    const int kg = tid >> 4;
    float s[8] = {0,0,0,0,0,0,0,0};
    __shared__ float sc[16];
    __shared__ float red[256];
    if (tid < 16) sc[tid] = 1.f;
    __syncthreads();
    const float cd = cdec[h];
    for (int n = 0; n < NC_; n++) {
        const int chunk = (b*NC_ + n)*H_ + h;
        const size_t zo = (size_t)chunk * (KD_*HD_);
        float invsc = 1.f / sc[v];
        #pragma unroll
        for (int i = 0; i < 8; i++)
            g_kvr[zo + (size_t)(kg*8+i)*HD_ + v0 + v] = s[i] * invsc;
        if (tid < 16) g_csc[chunk*HD_ + v0 + tid] = sc[tid];
        float p = 0.f;
        #pragma unroll
        for (int i = 0; i < 8; i++) {
            s[i] = s[i]*cd + g_kv[zo + (size_t)(kg*8+i)*HD_ + v0 + v];
            p += fabsf(s[i]);
        }
        red[tid] = p;
        __syncthreads();
        if (tid < 16) {
            float sum = 0.f;
            #pragma unroll
            for (int j = 0; j < 16; j++) sum += red[j*16 + tid];
            sc[tid] = fmaxf(sum, 1.f);
        }
        __syncthreads();
    }
}

// ===== cross = (qr*idec) @ kv_rec + combine + LN + silu gate (merged passes) =====
#define CA_H  0
#define CA_L  34816
#define CB_H  69632
#define CB_L  106496
#define CPART 143360
#define CRCSC 147456
#define CRISC 148480
#define CROSS_SMEM 148992

__global__ void __launch_bounds__(256, 1)
cross_mma(const float* __restrict__ idec)
{
    extern __shared__ __align__(128) char sm[];
    const uint32_t sb = smem_u32(sm);
    const int tid = threadIdx.x;
    const int wid = tid >> 5, lane = tid & 31;
    const int wm = wid & 1, wn = wid >> 1;
    const int g = lane >> 2, q = lane & 3;
    const int z = blockIdx.x, chunk = z >> 1, hf = z & 1;
    const int b = chunk / (NC_*H_);
    const int n = (chunk / H_) % NC_;
    const int h = chunk % H_;
    const int row0 = hf * 128;
    const int lrow8 = (lane & 7) + ((lane >> 3) & 1) * 8;
    const int koffB = (lane >> 4) * 16;

    {
        float c = g_csc[chunk*HD_ + tid];
        ((float*)(sm + CRCSC))[tid] = 1.f / c;
        if (tid < 128) {
            float s = g_isc[chunk*CH_ + row0 + tid];
            ((float*)(sm + CRISC))[tid] = 1.f / fmaxf(s, 1.f);
        }
    }
    {
        const float* qsrc = g_q + ((size_t)(b*T_ + n*CH_ + row0)) * E_ + h*KD_;
        const int r_ = tid >> 4, c_ = (tid & 15) * 8;
        #pragma unroll
        for (int p = 0; p < 8; p++) {
            int r = p * 16 + r_;
            float aw = idec[h*CH_ + row0 + r];
            float4 u0 = *(const float4*)(qsrc + (size_t)r * E_ + c_);
            float4 u1 = *(const float4*)(qsrc + (size_t)r * E_ + c_ + 4);
            u0.x *= aw; u0.y *= aw; u0.z *= aw; u0.w *= aw;
            u1.x *= aw; u1.y *= aw; u1.z *= aw; u1.w *= aw;
            uint4 hi, lo; split8(u0, u1, hi, lo);
            *(uint4*)(sm + CA_H + r * 272 + c_ * 2) = hi;
            *(uint4*)(sm + CA_L + r * 272 + c_ * 2) = lo;
        }
    }

    float acc[4][8][4] = {};
    const float* kvrsrc = g_kvr + (size_t)chunk * (KD_*HD_);

    for (int sl = 0; sl < 2; sl++) {
        __syncthreads();
        {
            const int d2 = (tid >> 6) << 1;
            const int c_ = (tid & 63) * 4;
            #pragma unroll
            for (int p = 0; p < 8; p++) {
                int dl = p * 8 + d2;
                int kd = sl * 64 + dl;
                float4 ua = *(const float4*)(kvrsrc + (size_t)kd * HD_ + c_);
                float4 ub = *(const float4*)(kvrsrc + (size_t)(kd + 1) * HD_ + c_);
                const float fa[4] = {ua.x, ua.y, ua.z, ua.w};
                const float fb[4] = {ub.x, ub.y, ub.z, ub.w};
                #pragma unroll
                for (int j = 0; j < 4; j++) {
                    uint32_t hi, lo;
                    split2(fa[j], fb[j], hi, lo);
                    *(uint32_t*)(sm + CB_H + (c_ + j) * 144 + dl * 2) = hi;
                    *(uint32_t*)(sm + CB_L + (c_ + j) * 144 + dl * 2) = lo;
                }
            }
        }
        __syncthreads();
        const uint32_t aH = sb + CA_H + (uint32_t)((wm*64 + lrow8) * 272 + sl * 128 + koffB);
        const uint32_t aL = sb + CA_L + (uint32_t)((wm*64 + lrow8) * 272 + sl * 128 + koffB);
        const uint32_t bH = sb + CB_H + (uint32_t)((wn*64 + lrow8) * 144 + koffB);
        const uint32_t bL = sb + CB_L + (uint32_t)((wn*64 + lrow8) * 144 + koffB);
        #pragma unroll
        for (int ks = 0; ks < 4; ks++) {
            const uint32_t kb = ks * 32;
            uint32_t afH[4][4], afL[4][4];
            #pragma unroll
            for (int mf = 0; mf < 4; mf++) {
                ldm_x4(afH[mf], aH + mf * 16 * 272 + kb);
                ldm_x4(afL[mf], aL + mf * 16 * 272 + kb);
            }
            uint32_t bfH[8][2], bfL[8][2];
            #pragma unroll
            for (int nf2 = 0; nf2 < 4; nf2++) {
                uint32_t t4[4];
                ldm_x4(t4, bH + nf2 * 16 * 144 + kb);
                unpack_b(t4, bfH[2*nf2], bfH[2*nf2+1]);
                ldm_x4(t4, bL + nf2 * 16 * 144 + kb);
                unpack_b(t4, bfL[2*nf2], bfL[2*nf2+1]);
            }
            #pragma unroll
            for (int mf = 0; mf < 4; mf++)
                #pragma unroll
                for (int nf = 0; nf < 8; nf++) {
                    mma_f16(acc[mf][nf], afH[mf], bfH[nf]);
                    mma_f16(acc[mf][nf], afH[mf], bfL[nf]);
                    mma_f16(acc[mf][nf], afL[mf], bfH[nf]);
                }
        }
    }

    const __half* innp = g_innerh + (size_t)chunk * (CH_*HD_) + (size_t)row0 * HD_;
    const float* rcsc = (const float*)(sm + CRCSC);
    const float* risc = (const float*)(sm + CRISC);
    float* part = (float*)(sm + CPART);

    #pragma unroll
    for (int mf = 0; mf < 4; mf++) {
        const int r0 = wm*64 + mf*16 + g, r1 = r0 + 8;
        const float i0 = risc[r0], i1 = risc[r1];
        float s0 = 0.f, q0 = 0.f, s1 = 0.f, q1 = 0.f;
        #pragma unroll
        for (int nf = 0; nf < 8; nf++) {
            const int c0 = wn*64 + nf*8 + q*2;
            const float rc0 = rcsc[c0], rc1 = rcsc[c0+1];
            float2 in0 = __half22float2(*(const __half2*)(innp + (size_t)r0 * HD_ + c0));
            float2 in1 = __half22float2(*(const __half2*)(innp + (size_t)r1 * HD_ + c0));
            float o00 = in0.x * rc0 + acc[mf][nf][0] * i0;
            float o01 = in0.y * rc1 + acc[mf][nf][1] * i0;
            float o10 = in1.x * rc0 + acc[mf][nf][2] * i1;
            float o11 = in1.y * rc1 + acc[mf][nf][3] * i1;
            acc[mf][nf][0] = o00; acc[mf][nf][1] = o01;
            acc[mf][nf][2] = o10; acc[mf][nf][3] = o11;
            s0 += o00 + o01; q0 += o00*o00 + o01*o01;
            s1 += o10 + o11; q1 += o10*o10 + o11*o11;
        }
        s0 += __shfl_xor_sync(0xffffffffu, s0, 1); s0 += __shfl_xor_sync(0xffffffffu, s0, 2);
        q0 += __shfl_xor_sync(0xffffffffu, q0, 1); q0 += __shfl_xor_sync(0xffffffffu, q0, 2);
        s1 += __shfl_xor_sync(0xffffffffu, s1, 1); s1 += __shfl_xor_sync(0xffffffffu, s1, 2);
        q1 += __shfl_xor_sync(0xffffffffu, q1, 1); q1 += __shfl_xor_sync(0xffffffffu, q1, 2);
        if (q == 0) {
            part[(r0*4 + wn)*2    ] = s0;
            part[(r0*4 + wn)*2 + 1] = q0;
            part[(r1*4 + wn)*2    ] = s1;
            part[(r1*4 + wn)*2 + 1] = q1;
        }
    }
    __syncthreads();

    const __half* gp = g_gth + ((size_t)(b*T_ + n*CH_ + row0)) * E2_ + h*HD_;
    __half* rop      = g_roh + ((size_t)(b*T_ + n*CH_ + row0)) * E2_ + h*HD_;
    #pragma unroll
    for (int mf = 0; mf < 4; mf++) {
        const int r0 = wm*64 + mf*16 + g, r1 = r0 + 8;
        float rs0 = part[(r0*4+0)*2] + part[(r0*4+1)*2] + part[(r0*4+2)*2] + part[(r0*4+3)*2];
        float rq0 = part[(r0*4+0)*2+1] + part[(r0*4+1)*2+1] + part[(r0*4+2)*2+1] + part[(r0*4+3)*2+1];
        float rs1 = part[(r1*4+0)*2] + part[(r1*4+1)*2] + part[(r1*4+2)*2] + part[(r1*4+3)*2];
        float rq1 = part[(r1*4+0)*2+1] + part[(r1*4+1)*2+1] + part[(r1*4+2)*2+1] + part[(r1*4+3)*2+1];
        const float mean0 = rs0 * (1.f/HD_);
        const float mean1 = rs1 * (1.f/HD_);
        const float rstd0 = rsqrtf(rq0 * (1.f/HD_) - mean0*mean0 + 1e-5f);
        const float rstd1 = rsqrtf(rq1 * (1.f/HD_) - mean1*mean1 + 1e-5f);
        #pragma unroll
        for (int nf = 0; nf < 8; nf++) {
            const int c0 = wn*64 + nf*8 + q*2;
            float2 gs0 = __half22float2(*(const __half2*)(gp + (size_t)r0 * E2_ + c0));
            float2 gs1 = __half22float2(*(const __half2*)(gp + (size_t)r1 * E2_ + c0));
            float o00 = gs0.x * (acc[mf][nf][0] - mean0) * rstd0;
            float o01 = gs0.y * (acc[mf][nf][1] - mean0) * rstd0;
            float o10 = gs1.x * (acc[mf][nf][2] - mean1) * rstd1;
            float o11 = gs1.y * (acc[mf][nf][3] - mean1) * rstd1;
            __half2 h0 = __floats2half2_rn(o00, o01);
            __half2 h1 = __floats2half2_rn(o10, o11);
            *(uint32_t*)(rop + (size_t)r0 * E2_ + c0) = *(uint32_t*)&h0;
            *(uint32_t*)(rop + (size_t)r1 * E2_ + c0) = *(uint32_t*)&h1;
        }
    }
}

// ================= launch =================
extern "C" void kernel_launch(void* const* d_in, const int* in_sizes, int n_in,
                              void* d_out, int out_size)
{
    const float* x    = (const float*)d_in[0];
    const float* sn   = (const float*)d_in[1];
    const float* cs   = (const float*)d_in[2];
    const float* mask = (const float*)d_in[3];
    const float* cdec = (const float*)d_in[4];
    const float* idec = (const float*)d_in[5];
    const float* Wq = (const float*)d_in[6];
    const float* bq = (const float*)d_in[7];
    const float* Wk = (const float*)d_in[8];
    const float* bk = (const float*)d_in[9];
    const float* Wv = (const float*)d_in[10];
    const float* bv = (const float*)d_in[11];
    const float* Wg = (const float*)d_in[12];
    const float* bg = (const float*)d_in[13];
    const float* Wo = (const float*)d_in[14];
    const float* bo = (const float*)d_in[15];
    float* out = (float*)d_out;

    __half *xh, *roh, *wqh, *wkh, *wvh, *wgh, *woh;
    cudaGetSymbolAddress((void**)&xh,  g_xh);
    cudaGetSymbolAddress((void**)&roh, g_roh);
    cudaGetSymbolAddress((void**)&wqh, g_wqh);
    cudaGetSymbolAddress((void**)&wkh, g_wkh);
    cudaGetSymbolAddress((void**)&wvh, g_wvh);
    cudaGetSymbolAddress((void**)&wgh, g_wgh);
    cudaGetSymbolAddress((void**)&woh, g_woh);

    cudaFuncSetAttribute(gemm_h, cudaFuncAttributeMaxDynamicSharedMemorySize, GEMMH_SMEM);
    cudaFuncSetAttribute(gemm_qk, cudaFuncAttributeMaxDynamicSharedMemorySize, GEMMH_SMEM);
    cudaFuncSetAttribute(gemm_vg, cudaFuncAttributeMaxDynamicSharedMemorySize, GEMMH_SMEM);
    cudaFuncSetAttribute(qki_kernel, cudaFuncAttributeMaxDynamicSharedMemorySize, QKI_SMEM);
    cudaFuncSetAttribute(kv_mma, cudaFuncAttributeMaxDynamicSharedMemorySize, KV_SMEM);
    cudaFuncSetAttribute(cross_mma, cudaFuncAttributeMaxDynamicSharedMemorySize, CROSS_SMEM);

    const int M = B_*T_;
    const float kscale = 1.0f / sqrtf((float)KD_);

    f2h_all<<<(F4_TOT + 255)/256, 256>>>(x, Wq, Wk, Wv, Wg, Wo);

    gemm_qk<<<dim3(E_/128,  M/128, 2), 256, GEMMH_SMEM>>>(xh, wqh, bq, wkh, bk, kscale, sn, cs);
    gemm_vg<<<dim3(E2_/128, M/128, 2), 256, GEMMH_SMEM>>>(xh, wvh, bv, wgh, bg);
    qki_kernel<<<2*NCHUNKS, 256, QKI_SMEM>>>(mask);
    kv_mma    <<<NCHUNKS,   256, KV_SMEM>>>(mask);
    scan_kernel<<<B_*H_*(HD_/16), 256>>>(cdec);
    cross_mma <<<2*NCHUNKS, 256, CROSS_SMEM>>>(idec);
    gemm_h<<<dim3(E_/128, M/128), 256, GEMMH_SMEM>>>(roh, woh, bo, out, E2_, E_, 1.f);
}

// round 16
// speedup vs baseline: 1.0328x; 1.0130x over previous
#include <cuda_runtime.h>
#include <cuda_fp16.h>
#include <math.h>
#include <stdint.h>

#define B_ 2
#define T_ 4096
#define E_ 2048
#define E2_ 4096
#define H_ 16
#define KD_ 128
#define HD_ 256
#define CH_ 256
#define NC_ 16
#define NCHUNKS (B_*NC_*H_)   // 512

// ================= scratch =================
__device__ float g_q [B_*T_*E_];
__device__ float g_k [B_*T_*E_];
__device__ float g_v [B_*T_*E2_];
__device__ float g_isc[NCHUNKS*CH_];
__device__ float g_kv [(size_t)NCHUNKS*KD_*HD_];
__device__ float g_kvr[(size_t)NCHUNKS*KD_*HD_];
__device__ float g_csc[NCHUNKS*HD_];
__device__ __half g_innerh[(size_t)NCHUNKS*CH_*HD_];
__device__ __half g_gth[B_*T_*E2_];
__device__ __half g_xh [B_*T_*E_];
__device__ __half g_roh[B_*T_*E2_];
__device__ __half g_wqh[E_*E_];
__device__ __half g_wkh[E_*E_];
__device__ __half g_wvh[(size_t)E2_*E_];
__device__ __half g_wgh[(size_t)E2_*E_];
__device__ __half g_woh[(size_t)E_*E2_];

// ================= helpers =================
__device__ __forceinline__ uint32_t smem_u32(const void* p) {
    uint32_t a;
    asm("{ .reg .u64 t; cvta.to.shared.u64 t, %1; cvt.u32.u64 %0, t; }" : "=r"(a) : "l"(p));
    return a;
}
__device__ __forceinline__ void cp16(uint32_t dst, const void* src) {
    asm volatile("cp.async.cg.shared.global [%0], [%1], 16;" :: "r"(dst), "l"(src));
}
__device__ __forceinline__ void cp_commit() { asm volatile("cp.async.commit_group;"); }
__device__ __forceinline__ void ldm_x4(uint32_t r[4], uint32_t addr) {
    asm volatile("ldmatrix.sync.aligned.m8n8.x4.shared.b16 {%0,%1,%2,%3}, [%4];"
        : "=r"(r[0]), "=r"(r[1]), "=r"(r[2]), "=r"(r[3]) : "r"(addr));
}
__device__ __forceinline__ void mma_f16(float c[4], const uint32_t a[4], const uint32_t b[2]) {
    asm volatile(
        "mma.sync.aligned.m16n8k16.row.col.f32.f16.f16.f32 "
        "{%0,%1,%2,%3}, {%4,%5,%6,%7}, {%8,%9}, {%0,%1,%2,%3};"
        : "+f"(c[0]), "+f"(c[1]), "+f"(c[2]), "+f"(c[3])
        : "r"(a[0]), "r"(a[1]), "r"(a[2]), "r"(a[3]), "r"(b[0]), "r"(b[1]));
}
__device__ __forceinline__ void split2(float a, float b, uint32_t &hi, uint32_t &lo) {
    __half ha = __float2half_rn(a), hb = __float2half_rn(b);
    __half2 H = __halves2half2(ha, hb);
    hi = *reinterpret_cast<uint32_t*>(&H);
    __half2 L = __floats2half2_rn(a - __half2float(ha), b - __half2float(hb));
    lo = *reinterpret_cast<uint32_t*>(&L);
}
__device__ __forceinline__ void unpack_b(const uint32_t t4[4], uint32_t b0[2], uint32_t b1[2]) {
    b0[0] = t4[0]; b0[1] = t4[2];
    b1[0] = t4[1]; b1[1] = t4[3];
}

// ================= fused f32 -> f16 converter =================
#define N4_X  (B_*T_*E_/4)
#define N4_WQ (E_*E_/4)
#define N4_WV (E2_*E_/4)
#define F4_0  N4_X
#define F4_1  (F4_0 + N4_WQ)
#define F4_2  (F4_1 + N4_WQ)
#define F4_3  (F4_2 + N4_WV)
#define F4_4  (F4_3 + N4_WV)
#define F4_TOT (F4_4 + N4_WV)

__global__ void f2h_all(const float* __restrict__ x,
                        const float* __restrict__ Wq, const float* __restrict__ Wk,
                        const float* __restrict__ Wv, const float* __restrict__ Wg,
                        const float* __restrict__ Wo)
{
    int i = blockIdx.x * blockDim.x + threadIdx.x;
    if (i >= F4_TOT) return;
    const float* src; __half* dst; int off;
    if (i < F4_0)      { src = x;  dst = g_xh;  off = i; }
    else if (i < F4_1) { src = Wq; dst = g_wqh; off = i - F4_0; }
    else if (i < F4_2) { src = Wk; dst = g_wkh; off = i - F4_1; }
    else if (i < F4_3) { src = Wv; dst = g_wvh; off = i - F4_2; }
    else if (i < F4_4) { src = Wg; dst = g_wgh; off = i - F4_3; }
    else               { src = Wo; dst = g_woh; off = i - F4_4; }
    float4 v = *(const float4*)(src + (size_t)off * 4);
    __half2 h[2];
    h[0] = __floats2half2_rn(v.x, v.y);
    h[1] = __floats2half2_rn(v.z, v.w);
    *(uint2*)(dst + (size_t)off * 4) = *(uint2*)h;
}

// ===== fp16 tensor-core GEMM core: 3-stage pipeline =====
#define BKH 64
#define TILEA 18432
#define STGB  36864
#define GEMMH_SMEM (3*STGB)

template<int ACT>
__device__ __forceinline__ void gemm_h_body(
    const __half* __restrict__ A, const __half* __restrict__ W,
    const float* __restrict__ bias, void* __restrict__ Cout,
    int K, int Ncols, float scale,
    const float* __restrict__ sn, const float* __restrict__ cs, char* smh)
{
    const int tid = threadIdx.x;
    const int wid = tid >> 5, lane = tid & 31;
    const int wm = wid & 1, wn = wid >> 1;
    const int g = lane >> 2, q = lane & 3;
    const int bx = blockIdx.x, by = blockIdx.y;

    const __half* Ab = A + (size_t)(by * 128) * K;
    const __half* Wb = W + (size_t)(bx * 128) * K;
    const uint32_t sb = smem_u32(smh);

    const int lr  = tid >> 1;
    const int lcu = (tid & 1) * 4;
    const int lrow8 = (lane & 7) + ((lane >> 3) & 1) * 8;
    const int koffB = (lane >> 4) * 16;
    const uint32_t ldoff = (uint32_t)(lr * 144 + lcu * 16);

    float acc[4][4][4] = {};
    const int NS = K / BKH;

    #pragma unroll
    for (int s = 0; s < 2; s++) {
        const uint32_t stg = sb + (uint32_t)s * STGB;
        const __half* As = Ab + (size_t)lr * K + s * BKH + lcu * 8;
        const __half* Ws = Wb + (size_t)lr * K + s * BKH + lcu * 8;
        #pragma unroll
        for (int i = 0; i < 4; i++) {
            cp16(stg + ldoff + i * 16, As + i * 8);
            cp16(stg + TILEA + ldoff + i * 16, Ws + i * 8);
        }
        cp_commit();
    }

    for (int s = 0; s < NS; s++) {
        asm volatile("cp.async.wait_group 1;");
        __syncthreads();
        if (s + 2 < NS) {
            const uint32_t stg = sb + (uint32_t)((s + 2) % 3) * STGB;
            const __half* As = Ab + (size_t)lr * K + (s + 2) * BKH + lcu * 8;
            const __half* Ws = Wb + (size_t)lr * K + (s + 2) * BKH + lcu * 8;
            #pragma unroll
            for (int i = 0; i < 4; i++) {
                cp16(stg + ldoff + i * 16, As + i * 8);
                cp16(stg + TILEA + ldoff + i * 16, Ws + i * 8);
            }
        }
        cp_commit();

        const uint32_t stg = sb + (uint32_t)(s % 3) * STGB;
        const uint32_t a_base = stg + (uint32_t)((wm * 64 + lrow8) * 144 + koffB);
        const uint32_t b_base = stg + TILEA + (uint32_t)((wn * 32 + lrow8) * 144 + koffB);
        #pragma unroll
        for (int ks = 0; ks < 4; ks++) {
            const uint32_t kc2 = ks * 32;
            uint32_t af[4][4];
            #pragma unroll
            for (int mf = 0; mf < 4; mf++) ldm_x4(af[mf], a_base + mf * 16 * 144 + kc2);
            uint32_t bf[4][2];
            #pragma unroll
            for (int nf2 = 0; nf2 < 2; nf2++) {
                uint32_t t4[4];
                ldm_x4(t4, b_base + nf2 * 16 * 144 + kc2);
                unpack_b(t4, bf[2*nf2], bf[2*nf2+1]);
            }
            #pragma unroll
            for (int mf = 0; mf < 4; mf++)
                #pragma unroll
                for (int nf = 0; nf < 4; nf++)
                    mma_f16(acc[mf][nf], af[mf], bf[nf]);
        }
    }

    #pragma unroll
    for (int mf = 0; mf < 4; mf++) {
        #pragma unroll
        for (int nf = 0; nf < 4; nf++) {
            const int row = by * 128 + wm * 64 + mf * 16 + g;
            const int col = bx * 128 + wn * 32 + nf * 8 + q * 2;
            const float b0 = bias[col], b1 = bias[col + 1];
            float o00 = (acc[mf][nf][0] + b0) * scale;
            float o01 = (acc[mf][nf][1] + b1) * scale;
            float o10 = (acc[mf][nf][2] + b0) * scale;
            float o11 = (acc[mf][nf][3] + b1) * scale;
            if (ACT == 2) {
                const int d = col & (KD_ - 1);
                const int t0 = row & (T_ - 1);
                const int t1 = t0 + 8;
                float c0 = cs[t0*KD_ + d], c1 = cs[t0*KD_ + d + 1];
                float s0 = sn[t0*KD_ + d], s1 = sn[t0*KD_ + d + 1];
                float r0 = o00 * c0 - o01 * s0;
                float r1 = o01 * c1 + o00 * s1;
                o00 = r0; o01 = r1;
                c0 = cs[t1*KD_ + d]; c1 = cs[t1*KD_ + d + 1];
                s0 = sn[t1*KD_ + d]; s1 = sn[t1*KD_ + d + 1];
                r0 = o10 * c0 - o11 * s0;
                r1 = o11 * c1 + o10 * s1;
                o10 = r0; o11 = r1;
            }
            if (ACT == 1) {
                __half* C = (__half*)Cout;
                float s00 = o00 / (1.f + expf(-o00));
                float s01 = o01 / (1.f + expf(-o01));
                float s10 = o10 / (1.f + expf(-o10));
                float s11 = o11 / (1.f + expf(-o11));
                __half2 h0 = __floats2half2_rn(s00, s01);
                __half2 h1 = __floats2half2_rn(s10, s11);
                *(uint32_t*)(C + (size_t)row * Ncols + col) = *(uint32_t*)&h0;
                *(uint32_t*)(C + (size_t)(row + 8) * Ncols + col) = *(uint32_t*)&h1;
            } else {
                float* C = (float*)Cout;
                *(float2*)(C + (size_t)row * Ncols + col) = make_float2(o00, o01);
                *(float2*)(C + (size_t)(row + 8) * Ncols + col) = make_float2(o10, o11);
            }
        }
    }
}

__global__ void __launch_bounds__(256)
gemm_qk(const __half* __restrict__ A,
        const __half* __restrict__ Wq, const float* __restrict__ bq,
        const __half* __restrict__ Wk, const float* __restrict__ bk,
        float kscale,
        const float* __restrict__ sn, const float* __restrict__ cs)
{
    extern __shared__ __align__(128) char smh[];
    if (blockIdx.z == 0)
        gemm_h_body<2>(A, Wq, bq, g_q, E_, E_, 1.f, sn, cs, smh);
    else
        gemm_h_body<2>(A, Wk, bk, g_k, E_, E_, kscale, sn, cs, smh);
}

__global__ void __launch_bounds__(256)
gemm_vg(const __half* __restrict__ A,
        const __half* __restrict__ Wv, const float* __restrict__ bv,
        const __half* __restrict__ Wg, const float* __restrict__ bg)
{
    extern __shared__ __align__(128) char smh[];
    if (blockIdx.z == 0)
        gemm_h_body<0>(A, Wv, bv, g_v, E_, E2_, 1.f, nullptr, nullptr, smh);
    else
        gemm_h_body<1>(A, Wg, bg, g_gth, E_, E2_, 1.f, nullptr, nullptr, smh);
}

__global__ void __launch_bounds__(256)
gemm_h(const __half* __restrict__ A, const __half* __restrict__ W,
       const float* __restrict__ bias, float* __restrict__ C,
       int K, int Ncols, float scale)
{
    extern __shared__ __align__(128) char smh[];
    gemm_h_body<0>(A, W, bias, C, K, Ncols, scale, nullptr, nullptr, smh);
}

// ===== fused qk -> mask -> isc -> inner =====
// phase 1 (q@kT): plain fp16 (rn), single pass; phase 2 (qkm@v): full split
#define P1   272
#define AQH_ 0
#define BKHo 34816
#define PQ   528
#define QKHo 0
#define QKLo 67584
#define PV   144
#define VHo  135168
#define VLo  172032
#define ISCP 208896
#define ISCS 210944
#define QKI_SMEM 211456

__global__ void __launch_bounds__(256, 1)
qki_kernel(const float* __restrict__ mask)
{
    extern __shared__ __align__(128) char sm[];
    const uint32_t sb = smem_u32(sm);
    const int tid = threadIdx.x;
    const int wid = tid >> 5, lane = tid & 31;
    const int wm = wid & 1, wn = wid >> 1;
    const int g = lane >> 2, q = lane & 3;
    const int z = blockIdx.x, chunk = z >> 1, hf = z & 1;
    const int b = chunk / (NC_*H_);
    const int n = (chunk / H_) % NC_;
    const int h = chunk % H_;
    const int row0 = hf * 128;

    const int lrow8 = (lane & 7) + ((lane >> 3) & 1) * 8;
    const int koffB = (lane >> 4) * 16;

    const float* qsrc = g_q + ((size_t)(b*T_ + n*CH_ + row0)) * E_ + h*KD_;
    const float* ksrc = g_k + ((size_t)(b*T_ + n*CH_)) * E_ + h*KD_;
    {
        const int r_ = tid >> 4, c_ = (tid & 15) * 8;
        #pragma unroll
        for (int p = 0; p < 8; p++) {
            int r = p * 16 + r_;
            float4 u0 = *(const float4*)(qsrc + (size_t)r * E_ + c_);
            float4 u1 = *(const float4*)(qsrc + (size_t)r * E_ + c_ + 4);
            uint4 hi;
            __half2 t;
            t = __floats2half2_rn(u0.x, u0.y); hi.x = *(uint32_t*)&t;
            t = __floats2half2_rn(u0.z, u0.w); hi.y = *(uint32_t*)&t;
            t = __floats2half2_rn(u1.x, u1.y); hi.z = *(uint32_t*)&t;
            t = __floats2half2_rn(u1.z, u1.w); hi.w = *(uint32_t*)&t;
            *(uint4*)(sm + AQH_ + r * P1 + c_ * 2) = hi;
        }
        #pragma unroll
        for (int p = 0; p < 16; p++) {
            int r = p * 16 + r_;
            float4 u0 = *(const float4*)(ksrc + (size_t)r * E_ + c_);
            float4 u1 = *(const float4*)(ksrc + (size_t)r * E_ + c_ + 4);
            uint4 hi;
            __half2 t;
            t = __floats2half2_rn(u0.x, u0.y); hi.x = *(uint32_t*)&t;
            t = __floats2half2_rn(u0.z, u0.w); hi.y = *(uint32_t*)&t;
            t = __floats2half2_rn(u1.x, u1.y); hi.z = *(uint32_t*)&t;
            t = __floats2half2_rn(u1.z, u1.w); hi.w = *(uint32_t*)&t;
            *(uint4*)(sm + BKHo + r * P1 + c_ * 2) = hi;
        }
    }
    __syncthreads();

    float acc[4][8][4] = {};

    // ---- phase 1: qk, plain fp16, single pass ----
    {
        const uint32_t aH = sb + AQH_ + (uint32_t)((wm*64 + lrow8) * P1 + koffB);
        const uint32_t bH = sb + BKHo + (uint32_t)((wn*64 + lrow8) * P1 + koffB);
        #pragma unroll
        for (int ks = 0; ks < 8; ks++) {
            const uint32_t kb = ks * 32;
            uint32_t af[4][4];
            #pragma unroll
            for (int mf = 0; mf < 4; mf++) ldm_x4(af[mf], aH + mf * 16 * P1 + kb);
            uint32_t bf[8][2];
            #pragma unroll
            for (int nf2 = 0; nf2 < 4; nf2++) {
                uint32_t t4[4];
                ldm_x4(t4, bH + nf2 * 16 * P1 + kb);
                unpack_b(t4, bf[2*nf2], bf[2*nf2+1]);
            }
            #pragma unroll
            for (int mf = 0; mf < 4; mf++)
                #pragma unroll
                for (int nf = 0; nf < 8; nf++)
                    mma_f16(acc[mf][nf], af[mf], bf[nf]);
        }
    }
    __syncthreads();

    {
        float psl[4] = {0,0,0,0}, psh[4] = {0,0,0,0};
        const float* mbase = mask + (size_t)h * (CH_*CH_) + (size_t)row0 * CH_;
        #pragma unroll
        for (int mf = 0; mf < 4; mf++) {
            const int r0 = wm*64 + mf*16 + g, r1 = r0 + 8;
            const float* m0 = mbase + (size_t)r0 * CH_;
            const float* m1 = mbase + (size_t)r1 * CH_;
            #pragma unroll
            for (int nf = 0; nf < 8; nf++) {
                const int c0 = wn*64 + nf*8 + q*2;
                float v00 = acc[mf][nf][0] * m0[c0];
                float v01 = acc[mf][nf][1] * m0[c0+1];
                float v10 = acc[mf][nf][2] * m1[c0];
                float v11 = acc[mf][nf][3] * m1[c0+1];
                psl[mf] += fabsf(v00) + fabsf(v01);
                psh[mf] += fabsf(v10) + fabsf(v11);
                uint32_t h0, l0, h1, l1;
                split2(v00, v01, h0, l0);
                split2(v10, v11, h1, l1);
                *(uint32_t*)(sm + QKHo + r0 * PQ + c0 * 2) = h0;
                *(uint32_t*)(sm + QKLo + r0 * PQ + c0 * 2) = l0;
                *(uint32_t*)(sm + QKHo + r1 * PQ + c0 * 2) = h1;
                *(uint32_t*)(sm + QKLo + r1 * PQ + c0 * 2) = l1;
            }
        }
        float* iscp = (float*)(sm + ISCP);
        #pragma unroll
        for (int mf = 0; mf < 4; mf++) {
            float pl = psl[mf], ph = psh[mf];
            pl += __shfl_xor_sync(0xffffffffu, pl, 1);
            pl += __shfl_xor_sync(0xffffffffu, pl, 2);
            ph += __shfl_xor_sync(0xffffffffu, ph, 1);
            ph += __shfl_xor_sync(0xffffffffu, ph, 2);
            if (q == 0) {
                iscp[(wm*64 + mf*16 + g) * 4 + wn] = pl;
                iscp[(wm*64 + mf*16 + g + 8) * 4 + wn] = ph;
            }
        }
    }
    __syncthreads();
    if (tid < 128) {
        const float* ip = (const float*)(sm + ISCP) + tid * 4;
        float s = ip[0] + ip[1] + ip[2] + ip[3];
        g_isc[chunk*CH_ + row0 + tid] = s;
        ((float*)(sm + ISCS))[tid] = fmaxf(s, 1.f);
    }

    #pragma unroll
    for (int mf = 0; mf < 4; mf++)
        #pragma unroll
        for (int nf = 0; nf < 8; nf++)
            #pragma unroll
            for (int e = 0; e < 4; e++) acc[mf][nf][e] = 0.f;

    const float* vsrc = g_v + ((size_t)(b*T_ + n*CH_)) * E2_ + h*HD_;
    for (int sl = 0; sl < 4; sl++) {
        __syncthreads();
        {
            const int d2 = (tid >> 6) << 1;
            const int c_ = (tid & 63) * 4;
            #pragma unroll
            for (int p = 0; p < 8; p++) {
                int dl = p * 8 + d2;
                int d = sl * 64 + dl;
                float4 ua = *(const float4*)(vsrc + (size_t)d * E2_ + c_);
                float4 ub = *(const float4*)(vsrc + (size_t)(d + 1) * E2_ + c_);
                const float fa[4] = {ua.x, ua.y, ua.z, ua.w};
                const float fb[4] = {ub.x, ub.y, ub.z, ub.w};
                #pragma unroll
                for (int j = 0; j < 4; j++) {
                    uint32_t hi, lo;
                    split2(fa[j], fb[j], hi, lo);
                    *(uint32_t*)(sm + VHo + (c_ + j) * PV + dl * 2) = hi;
                    *(uint32_t*)(sm + VLo + (c_ + j) * PV + dl * 2) = lo;
                }
            }
        }
        __syncthreads();
        const uint32_t aH = sb + QKHo + (uint32_t)((wm*64 + lrow8) * PQ + sl * 128 + koffB);
        const uint32_t aL = sb + QKLo + (uint32_t)((wm*64 + lrow8) * PQ + sl * 128 + koffB);
        const uint32_t bH = sb + VHo + (uint32_t)((wn*64 + lrow8) * PV + koffB);
        const uint32_t bL = sb + VLo + (uint32_t)((wn*64 + lrow8) * PV + koffB);
        #pragma unroll
        for (int ks = 0; ks < 4; ks++) {
            const uint32_t kb = ks * 32;
            uint32_t afH[4][4], afL[4][4];
            #pragma unroll
            for (int mf = 0; mf < 4; mf++) {
                ldm_x4(afH[mf], aH + mf * 16 * PQ + kb);
                ldm_x4(afL[mf], aL + mf * 16 * PQ + kb);
            }
            uint32_t bfH[8][2], bfL[8][2];
            #pragma unroll
            for (int nf2 = 0; nf2 < 4; nf2++) {
                uint32_t t4[4];
                ldm_x4(t4, bH + nf2 * 16 * PV + kb);
                unpack_b(t4, bfH[2*nf2], bfH[2*nf2+1]);
                ldm_x4(t4, bL + nf2 * 16 * PV + kb);
                unpack_b(t4, bfL[2*nf2], bfL[2*nf2+1]);
            }
            #pragma unroll
            for (int mf = 0; mf < 4; mf++)
                #pragma unroll
                for (int nf = 0; nf < 8; nf++) {
                    mma_f16(acc[mf][nf], afH[mf], bfH[nf]);
                    mma_f16(acc[mf][nf], afH[mf], bfL[nf]);
                    mma_f16(acc[mf][nf], afL[mf], bfH[nf]);
                }
        }
    }

    {
        const float* iscs = (const float*)(sm + ISCS);
        __half* op = g_innerh + (size_t)chunk * (CH_*HD_) + (size_t)row0 * HD_;
        #pragma unroll
        for (int mf = 0; mf < 4; mf++) {
            const int r0 = wm*64 + mf*16 + g, r1 = r0 + 8;
            const float inv0 = 1.f / iscs[r0];
            const float inv1 = 1.f / iscs[r1];
            #pragma unroll
            for (int nf = 0; nf < 8; nf++) {
                const int c0 = wn*64 + nf*8 + q*2;
                __half2 h0 = __floats2half2_rn(acc[mf][nf][0] * inv0, acc[mf][nf][1] * inv0);
                __half2 h1 = __floats2half2_rn(acc[mf][nf][2] * inv1, acc[mf][nf][3] * inv1);
                *(uint32_t*)(op + (size_t)r0 * HD_ + c0) = *(uint32_t*)&h0;
                *(uint32_t*)(op + (size_t)r1 * HD_ + c0) = *(uint32_t*)&h1;
            }
        }
    }
}

// ===== kv = (w*k)^T @ v  (split-fp16, merged passes) =====
#define KT_H 0
#define KT_L 18432
#define KVT_H 36864
#define KVT_L 73728
#define KV_SMEM 110592

__global__ void __launch_bounds__(256, 1)
kv_mma(const float* __restrict__ mask)
{
    extern __shared__ __align__(128) char sm[];
    const uint32_t sb = smem_u32(sm);
    const int tid = threadIdx.x;
    const int wid = tid >> 5, lane = tid & 31;
    const int wm = wid & 1, wn = wid >> 1;
    const int g = lane >> 2, q = lane & 3;
    const int chunk = blockIdx.x;
    const int b = chunk / (NC_*H_);
    const int n = (chunk / H_) % NC_;
    const int h = chunk % H_;
    const int lrow8 = (lane & 7) + ((lane >> 3) & 1) * 8;
    const int koffB = (lane >> 4) * 16;

    const float* ksrc = g_k + ((size_t)(b*T_ + n*CH_)) * E_ + h*KD_;
    const float* vsrc = g_v + ((size_t)(b*T_ + n*CH_)) * E2_ + h*HD_;
    const float* wrow = mask + (size_t)h * (CH_*CH_) + (size_t)(CH_-1) * CH_;

    float acc[4][8][4] = {};

    for (int sl = 0; sl < 4; sl++) {
        __syncthreads();
        {
            const int cp = (tid >> 3) << 1;
            const int kb_ = (tid & 7) * 16;
            const int c = sl * 64 + cp;
            const float w0 = wrow[c], w1 = wrow[c + 1];
            const float* s0 = ksrc + (size_t)c * E_;
            const float* s1 = ksrc + (size_t)(c + 1) * E_;
            #pragma unroll
            for (int p = 0; p < 4; p++) {
                const int kd = kb_ + p * 4;
                float4 u0 = *(const float4*)(s0 + kd);
                float4 u1 = *(const float4*)(s1 + kd);
                const float f0[4] = {u0.x * w0, u0.y * w0, u0.z * w0, u0.w * w0};
                const float f1[4] = {u1.x * w1, u1.y * w1, u1.z * w1, u1.w * w1};
                #pragma unroll
                for (int j = 0; j < 4; j++) {
                    uint32_t hi, lo;
                    split2(f0[j], f1[j], hi, lo);
                    *(uint32_t*)(sm + KT_H + (kd + j) * 144 + cp * 2) = hi;
                    *(uint32_t*)(sm + KT_L + (kd + j) * 144 + cp * 2) = lo;
                }
            }
        }
        {
            const int d2 = (tid >> 6) << 1;
            const int c_ = (tid & 63) * 4;
            #pragma unroll
            for (int p = 0; p < 8; p++) {
                int dl = p * 8 + d2;
                int c = sl * 64 + dl;
                float4 ua = *(const float4*)(vsrc + (size_t)c * E2_ + c_);
                float4 ub = *(const float4*)(vsrc + (size_t)(c + 1) * E2_ + c_);
                const float fa[4] = {ua.x, ua.y, ua.z, ua.w};
                const float fb[4] = {ub.x, ub.y, ub.z, ub.w};
                #pragma unroll
                for (int j = 0; j < 4; j++) {
                    uint32_t hi, lo;
                    split2(fa[j], fb[j], hi, lo);
                    *(uint32_t*)(sm + KVT_H + (c_ + j) * 144 + dl * 2) = hi;
                    *(uint32_t*)(sm + KVT_L + (c_ + j) * 144 + dl * 2) = lo;
                }
            }
        }
        __syncthreads();
        const uint32_t aH = sb + KT_H + (uint32_t)((wm*64 + lrow8) * 144 + koffB);
        const uint32_t aL = sb + KT_L + (uint32_t)((wm*64 + lrow8) * 144 + koffB);
        const uint32_t bH = sb + KVT_H + (uint32_t)((wn*64 + lrow8) * 144 + koffB);
        const uint32_t bL = sb + KVT_L + (uint32_t)((wn*64 + lrow8) * 144 + koffB);
        #pragma unroll
        for (int ks = 0; ks < 4; ks++) {
            const uint32_t kb = ks * 32;
            uint32_t afH[4][4], afL[4][4];
            #pragma unroll
            for (int mf = 0; mf < 4; mf++) {
                ldm_x4(afH[mf], aH + mf * 16 * 144 + kb);
                ldm_x4(afL[mf], aL + mf * 16 * 144 + kb);
            }
            uint32_t bfH[8][2], bfL[8][2];
            #pragma unroll
            for (int nf2 = 0; nf2 < 4; nf2++) {
                uint32_t t4[4];
                ldm_x4(t4, bH + nf2 * 16 * 144 + kb);
                unpack_b(t4, bfH[2*nf2], bfH[2*nf2+1]);
                ldm_x4(t4, bL + nf2 * 16 * 144 + kb);
                unpack_b(t4, bfL[2*nf2], bfL[2*nf2+1]);
            }
            #pragma unroll
            for (int mf = 0; mf < 4; mf++)
                #pragma unroll
                for (int nf = 0; nf < 8; nf++) {
                    mma_f16(acc[mf][nf], afH[mf], bfH[nf]);
                    mma_f16(acc[mf][nf], afH[mf], bfL[nf]);
                    mma_f16(acc[mf][nf], afL[mf], bfH[nf]);
                }
        }
    }

    float* op = g_kv + (size_t)chunk * (KD_*HD_);
    #pragma unroll
    for (int mf = 0; mf < 4; mf++) {
        const int r0 = wm*64 + mf*16 + g, r1 = r0 + 8;
        #pragma unroll
        for (int nf = 0; nf < 8; nf++) {
            const int c0 = wn*64 + nf*8 + q*2;
            *(float2*)(op + (size_t)r0 * HD_ + c0) = make_float2(acc[mf][nf][0], acc[mf][nf][1]);
            *(float2*)(op + (size_t)r1 * HD_ + c0) = make_float2(acc[mf][nf][2], acc[mf][nf][3]);
        }
    }
}

// ---------------- cross-chunk scan ----------------
__global__ __launch_bounds__(256)
void scan_kernel(const float* __restrict__ cdec)
{
    const int vb = blockIdx.x & 15;
    const int bh = blockIdx.x >> 4;
    const int b = bh / H_, h = bh % H_;
    const int v0 = vb * 16;
    const int tid = threadIdx.x;
    const int v = tid & 15;
    const int kg = tid >> 4;
    float s[8] = {0,0,0,0,0,0,0,0};
    __shared__ float sc[16];
    __shared__ float red[256];
    if (tid < 16) sc[tid] = 1.f;
    __syncthreads();
    const float cd = cdec[h];
    for (int n = 0; n < NC_; n++) {
        const int chunk = (b*NC_ + n)*H_ + h;
        const size_t zo = (size_t)chunk * (KD_*HD_);
        float invsc = 1.f / sc[v];
        #pragma unroll
        for (int i = 0; i < 8; i++)
            g_kvr[zo + (size_t)(kg*8+i)*HD_ + v0 + v] = s[i] * invsc;
        if (tid < 16) g_csc[chunk*HD_ + v0 + tid] = sc[tid];
        float p = 0.f;
        #pragma unroll
        for (int i = 0; i < 8; i++) {
            s[i] = s[i]*cd + g_kv[zo + (size_t)(kg*8+i)*HD_ + v0 + v];
            p += fabsf(s[i]);
        }
        red[tid] = p;
        __syncthreads();
        if (tid < 16) {
            float sum = 0.f;
            #pragma unroll
            for (int j = 0; j < 16; j++) sum += red[j*16 + tid];
            sc[tid] = fmaxf(sum, 1.f);
        }
        __syncthreads();
    }
}

// ===== cross = (qr*idec) @ kv_rec + combine + LN + silu gate (merged passes) =====
#define CA_H  0
#define CA_L  34816
#define CB_H  69632
#define CB_L  106496
#define CPART 143360
#define CRCSC 147456
#define CRISC 148480
#define CROSS_SMEM 148992

__global__ void __launch_bounds__(256, 1)
cross_mma(const float* __restrict__ idec)
{
    extern __shared__ __align__(128) char sm[];
    const uint32_t sb = smem_u32(sm);
    const int tid = threadIdx.x;
    const int wid = tid >> 5, lane = tid & 31;
    const int wm = wid & 1, wn = wid >> 1;
    const int g = lane >> 2, q = lane & 3;
    const int z = blockIdx.x, chunk = z >> 1, hf = z & 1;
    const int b = chunk / (NC_*H_);
    const int n = (chunk / H_) % NC_;
    const int h = chunk % H_;
    const int row0 = hf * 128;
    const int lrow8 = (lane & 7) + ((lane >> 3) & 1) * 8;
    const int koffB = (lane >> 4) * 16;

    {
        float c = g_csc[chunk*HD_ + tid];
        ((float*)(sm + CRCSC))[tid] = 1.f / c;
        if (tid < 128) {
            float s = g_isc[chunk*CH_ + row0 + tid];
            ((float*)(sm + CRISC))[tid] = 1.f / fmaxf(s, 1.f);
        }
    }
    {
        const float* qsrc = g_q + ((size_t)(b*T_ + n*CH_ + row0)) * E_ + h*KD_;
        const int r_ = tid >> 4, c_ = (tid & 15) * 8;
        #pragma unroll
        for (int p = 0; p < 8; p++) {
            int r = p * 16 + r_;
            float aw = idec[h*CH_ + row0 + r];
            float4 u0 = *(const float4*)(qsrc + (size_t)r * E_ + c_);
            float4 u1 = *(const float4*)(qsrc + (size_t)r * E_ + c_ + 4);
            u0.x *= aw; u0.y *= aw; u0.z *= aw; u0.w *= aw;
            u1.x *= aw; u1.y *= aw; u1.z *= aw; u1.w *= aw;
            uint4 hi, lo;
            split2(u0.x, u0.y, hi.x, lo.x);
            split2(u0.z, u0.w, hi.y, lo.y);
            split2(u1.x, u1.y, hi.z, lo.z);
            split2(u1.z, u1.w, hi.w, lo.w);
            *(uint4*)(sm + CA_H + r * 272 + c_ * 2) = hi;
            *(uint4*)(sm + CA_L + r * 272 + c_ * 2) = lo;
        }
    }

    float acc[4][8][4] = {};
    const float* kvrsrc = g_kvr + (size_t)chunk * (KD_*HD_);

    for (int sl = 0; sl < 2; sl++) {
        __syncthreads();
        {
            const int d2 = (tid >> 6) << 1;
            const int c_ = (tid & 63) * 4;
            #pragma unroll
            for (int p = 0; p < 8; p++) {
                int dl = p * 8 + d2;
                int kd = sl * 64 + dl;
                float4 ua = *(const float4*)(kvrsrc + (size_t)kd * HD_ + c_);
                float4 ub = *(const float4*)(kvrsrc + (size_t)(kd + 1) * HD_ + c_);
                const float fa[4] = {ua.x, ua.y, ua.z, ua.w};
                const float fb[4] = {ub.x, ub.y, ub.z, ub.w};
                #pragma unroll
                for (int j = 0; j < 4; j++) {
                    uint32_t hi, lo;
                    split2(fa[j], fb[j], hi, lo);
                    *(uint32_t*)(sm + CB_H + (c_ + j) * 144 + dl * 2) = hi;
                    *(uint32_t*)(sm + CB_L + (c_ + j) * 144 + dl * 2) = lo;
                }
            }
        }
        __syncthreads();
        const uint32_t aH = sb + CA_H + (uint32_t)((wm*64 + lrow8) * 272 + sl * 128 + koffB);
        const uint32_t aL = sb + CA_L + (uint32_t)((wm*64 + lrow8) * 272 + sl * 128 + koffB);
        const uint32_t bH = sb + CB_H + (uint32_t)((wn*64 + lrow8) * 144 + koffB);
        const uint32_t bL = sb + CB_L + (uint32_t)((wn*64 + lrow8) * 144 + koffB);
        #pragma unroll
        for (int ks = 0; ks < 4; ks++) {
            const uint32_t kb = ks * 32;
            uint32_t afH[4][4], afL[4][4];
            #pragma unroll
            for (int mf = 0; mf < 4; mf++) {
                ldm_x4(afH[mf], aH + mf * 16 * 272 + kb);
                ldm_x4(afL[mf], aL + mf * 16 * 272 + kb);
            }
            uint32_t bfH[8][2], bfL[8][2];
            #pragma unroll
            for (int nf2 = 0; nf2 < 4; nf2++) {
                uint32_t t4[4];
                ldm_x4(t4, bH + nf2 * 16 * 144 + kb);
                unpack_b(t4, bfH[2*nf2], bfH[2*nf2+1]);
                ldm_x4(t4, bL + nf2 * 16 * 144 + kb);
                unpack_b(t4, bfL[2*nf2], bfL[2*nf2+1]);
            }
            #pragma unroll
            for (int mf = 0; mf < 4; mf++)
                #pragma unroll
                for (int nf = 0; nf < 8; nf++) {
                    mma_f16(acc[mf][nf], afH[mf], bfH[nf]);
                    mma_f16(acc[mf][nf], afH[mf], bfL[nf]);
                    mma_f16(acc[mf][nf], afL[mf], bfH[nf]);
                }
        }
    }

    const __half* innp = g_innerh + (size_t)chunk * (CH_*HD_) + (size_t)row0 * HD_;
    const float* rcsc = (const float*)(sm + CRCSC);
    const float* risc = (const float*)(sm + CRISC);
    float* part = (float*)(sm + CPART);

    #pragma unroll
    for (int mf = 0; mf < 4; mf++) {
        const int r0 = wm*64 + mf*16 + g, r1 = r0 + 8;
        const float i0 = risc[r0], i1 = risc[r1];
        float s0 = 0.f, q0 = 0.f, s1 = 0.f, q1 = 0.f;
        #pragma unroll
        for (int nf = 0; nf < 8; nf++) {
            const int c0 = wn*64 + nf*8 + q*2;
            const float rc0 = rcsc[c0], rc1 = rcsc[c0+1];
            float2 in0 = __half22float2(*(const __half2*)(innp + (size_t)r0 * HD_ + c0));
            float2 in1 = __half22float2(*(const __half2*)(innp + (size_t)r1 * HD_ + c0));
            float o00 = in0.x * rc0 + acc[mf][nf][0] * i0;
            float o01 = in0.y * rc1 + acc[mf][nf][1] * i0;
            float o10 = in1.x * rc0 + acc[mf][nf][2] * i1;
            float o11 = in1.y * rc1 + acc[mf][nf][3] * i1;
            acc[mf][nf][0] = o00; acc[mf][nf][1] = o01;
            acc[mf][nf][2] = o10; acc[mf][nf][3] = o11;
            s0 += o00 + o01; q0 += o00*o00 + o01*o01;
            s1 += o10 + o11; q1 += o10*o10 + o11*o11;
        }
        s0 += __shfl_xor_sync(0xffffffffu, s0, 1); s0 += __shfl_xor_sync(0xffffffffu, s0, 2);
        q0 += __shfl_xor_sync(0xffffffffu, q0, 1); q0 += __shfl_xor_sync(0xffffffffu, q0, 2);
        s1 += __shfl_xor_sync(0xffffffffu, s1, 1); s1 += __shfl_xor_sync(0xffffffffu, s1, 2);
        q1 += __shfl_xor_sync(0xffffffffu, q1, 1); q1 += __shfl_xor_sync(0xffffffffu, q1, 2);
        if (q == 0) {
            part[(r0*4 + wn)*2    ] = s0;
            part[(r0*4 + wn)*2 + 1] = q0;
            part[(r1*4 + wn)*2    ] = s1;
            part[(r1*4 + wn)*2 + 1] = q1;
        }
    }
    __syncthreads();

    const __half* gp = g_gth + ((size_t)(b*T_ + n*CH_ + row0)) * E2_ + h*HD_;
    __half* rop      = g_roh + ((size_t)(b*T_ + n*CH_ + row0)) * E2_ + h*HD_;
    #pragma unroll
    for (int mf = 0; mf < 4; mf++) {
        const int r0 = wm*64 + mf*16 + g, r1 = r0 + 8;
        float rs0 = part[(r0*4+0)*2] + part[(r0*4+1)*2] + part[(r0*4+2)*2] + part[(r0*4+3)*2];
        float rq0 = part[(r0*4+0)*2+1] + part[(r0*4+1)*2+1] + part[(r0*4+2)*2+1] + part[(r0*4+3)*2+1];
        float rs1 = part[(r1*4+0)*2] + part[(r1*4+1)*2] + part[(r1*4+2)*2] + part[(r1*4+3)*2];
        float rq1 = part[(r1*4+0)*2+1] + part[(r1*4+1)*2+1] + part[(r1*4+2)*2+1] + part[(r1*4+3)*2+1];
        const float mean0 = rs0 * (1.f/HD_);
        const float mean1 = rs1 * (1.f/HD_);
        const float rstd0 = rsqrtf(rq0 * (1.f/HD_) - mean0*mean0 + 1e-5f);
        const float rstd1 = rsqrtf(rq1 * (1.f/HD_) - mean1*mean1 + 1e-5f);
        #pragma unroll
        for (int nf = 0; nf < 8; nf++) {
            const int c0 = wn*64 + nf*8 + q*2;
            float2 gs0 = __half22float2(*(const __half2*)(gp + (size_t)r0 * E2_ + c0));
            float2 gs1 = __half22float2(*(const __half2*)(gp + (size_t)r1 * E2_ + c0));
            float o00 = gs0.x * (acc[mf][nf][0] - mean0) * rstd0;
            float o01 = gs0.y * (acc[mf][nf][1] - mean0) * rstd0;
            float o10 = gs1.x * (acc[mf][nf][2] - mean1) * rstd1;
            float o11 = gs1.y * (acc[mf][nf][3] - mean1) * rstd1;
            __half2 h0 = __floats2half2_rn(o00, o01);
            __half2 h1 = __floats2half2_rn(o10, o11);
            *(uint32_t*)(rop + (size_t)r0 * E2_ + c0) = *(uint32_t*)&h0;
            *(uint32_t*)(rop + (size_t)r1 * E2_ + c0) = *(uint32_t*)&h1;
        }
    }
}

// ================= launch =================
extern "C" void kernel_launch(void* const* d_in, const int* in_sizes, int n_in,
                              void* d_out, int out_size)
{
    const float* x    = (const float*)d_in[0];
    const float* sn   = (const float*)d_in[1];
    const float* cs   = (const float*)d_in[2];
    const float* mask = (const float*)d_in[3];
    const float* cdec = (const float*)d_in[4];
    const float* idec = (const float*)d_in[5];
    const float* Wq = (const float*)d_in[6];
    const float* bq = (const float*)d_in[7];
    const float* Wk = (const float*)d_in[8];
    const float* bk = (const float*)d_in[9];
    const float* Wv = (const float*)d_in[10];
    const float* bv = (const float*)d_in[11];
    const float* Wg = (const float*)d_in[12];
    const float* bg = (const float*)d_in[13];
    const float* Wo = (const float*)d_in[14];
    const float* bo = (const float*)d_in[15];
    float* out = (float*)d_out;

    __half *xh, *roh, *wqh, *wkh, *wvh, *wgh, *woh;
    cudaGetSymbolAddress((void**)&xh,  g_xh);
    cudaGetSymbolAddress((void**)&roh, g_roh);
    cudaGetSymbolAddress((void**)&wqh, g_wqh);
    cudaGetSymbolAddress((void**)&wkh, g_wkh);
    cudaGetSymbolAddress((void**)&wvh, g_wvh);
    cudaGetSymbolAddress((void**)&wgh, g_wgh);
    cudaGetSymbolAddress((void**)&woh, g_woh);

    cudaFuncSetAttribute(gemm_h, cudaFuncAttributeMaxDynamicSharedMemorySize, GEMMH_SMEM);
    cudaFuncSetAttribute(gemm_qk, cudaFuncAttributeMaxDynamicSharedMemorySize, GEMMH_SMEM);
    cudaFuncSetAttribute(gemm_vg, cudaFuncAttributeMaxDynamicSharedMemorySize, GEMMH_SMEM);
    cudaFuncSetAttribute(qki_kernel, cudaFuncAttributeMaxDynamicSharedMemorySize, QKI_SMEM);
    cudaFuncSetAttribute(kv_mma, cudaFuncAttributeMaxDynamicSharedMemorySize, KV_SMEM);
    cudaFuncSetAttribute(cross_mma, cudaFuncAttributeMaxDynamicSharedMemorySize, CROSS_SMEM);

    const int M = B_*T_;
    const float kscale = 1.0f / sqrtf((float)KD_);

    f2h_all<<<(F4_TOT + 255)/256, 256>>>(x, Wq, Wk, Wv, Wg, Wo);

    gemm_qk<<<dim3(E_/128,  M/128, 2), 256, GEMMH_SMEM>>>(xh, wqh, bq, wkh, bk, kscale, sn, cs);
    gemm_vg<<<dim3(E2_/128, M/128, 2), 256, GEMMH_SMEM>>>(xh, wvh, bv, wgh, bg);
    qki_kernel<<<2*NCHUNKS, 256, QKI_SMEM>>>(mask);
    kv_mma    <<<NCHUNKS,   256, KV_SMEM>>>(mask);
    scan_kernel<<<B_*H_*(HD_/16), 256>>>(cdec);
    cross_mma <<<2*NCHUNKS, 256, CROSS_SMEM>>>(idec);
    gemm_h<<<dim3(E_/128, M/128), 256, GEMMH_SMEM>>>(roh, woh, bo, out, E2_, E_, 1.f);
}

// round 17
// speedup vs baseline: 1.1214x; 1.0858x over previous
#include <cuda_runtime.h>
#include <cuda_fp16.h>
#include <math.h>
#include <stdint.h>

#define B_ 2
#define T_ 4096
#define E_ 2048
#define E2_ 4096
#define H_ 16
#define KD_ 128
#define HD_ 256
#define CH_ 256
#define NC_ 16
#define NCHUNKS (B_*NC_*H_)   // 512

// ================= scratch =================
__device__ float g_q [B_*T_*E_];
__device__ float g_k [B_*T_*E_];
__device__ float g_v [B_*T_*E2_];
__device__ float g_isc[NCHUNKS*CH_];
__device__ float g_kv [(size_t)NCHUNKS*KD_*HD_];
__device__ float g_kvr[(size_t)NCHUNKS*KD_*HD_];
__device__ float g_csc[NCHUNKS*HD_];
__device__ __half g_innerh[(size_t)NCHUNKS*CH_*HD_];
__device__ __half g_gth[B_*T_*E2_];
__device__ __half g_xh [B_*T_*E_];
__device__ __half g_roh[B_*T_*E2_];
__device__ __half g_wqh[E_*E_];
__device__ __half g_wkh[E_*E_];
__device__ __half g_wvh[(size_t)E2_*E_];
__device__ __half g_wgh[(size_t)E2_*E_];
__device__ __half g_woh[(size_t)E_*E2_];

// ================= helpers =================
__device__ __forceinline__ uint32_t smem_u32(const void* p) {
    uint32_t a;
    asm("{ .reg .u64 t; cvta.to.shared.u64 t, %1; cvt.u32.u64 %0, t; }" : "=r"(a) : "l"(p));
    return a;
}
__device__ __forceinline__ void cp16(uint32_t dst, const void* src) {
    asm volatile("cp.async.cg.shared.global [%0], [%1], 16;" :: "r"(dst), "l"(src));
}
__device__ __forceinline__ void cp_commit() { asm volatile("cp.async.commit_group;"); }
__device__ __forceinline__ void ldm_x4(uint32_t r[4], uint32_t addr) {
    asm volatile("ldmatrix.sync.aligned.m8n8.x4.shared.b16 {%0,%1,%2,%3}, [%4];"
        : "=r"(r[0]), "=r"(r[1]), "=r"(r[2]), "=r"(r[3]) : "r"(addr));
}
__device__ __forceinline__ void mma_f16(float c[4], const uint32_t a[4], const uint32_t b[2]) {
    asm volatile(
        "mma.sync.aligned.m16n8k16.row.col.f32.f16.f16.f32 "
        "{%0,%1,%2,%3}, {%4,%5,%6,%7}, {%8,%9}, {%0,%1,%2,%3};"
        : "+f"(c[0]), "+f"(c[1]), "+f"(c[2]), "+f"(c[3])
        : "r"(a[0]), "r"(a[1]), "r"(a[2]), "r"(a[3]), "r"(b[0]), "r"(b[1]));
}
__device__ __forceinline__ void split2(float a, float b, uint32_t &hi, uint32_t &lo) {
    __half ha = __float2half_rn(a), hb = __float2half_rn(b);
    __half2 H = __halves2half2(ha, hb);
    hi = *reinterpret_cast<uint32_t*>(&H);
    __half2 L = __floats2half2_rn(a - __half2float(ha), b - __half2float(hb));
    lo = *reinterpret_cast<uint32_t*>(&L);
}
__device__ __forceinline__ uint32_t rnpack(float a, float b) {
    __half2 t = __floats2half2_rn(a, b);
    return *reinterpret_cast<uint32_t*>(&t);
}
__device__ __forceinline__ void unpack_b(const uint32_t t4[4], uint32_t b0[2], uint32_t b1[2]) {
    b0[0] = t4[0]; b0[1] = t4[2];
    b1[0] = t4[1]; b1[1] = t4[3];
}

// ================= fused f32 -> f16 converter =================
#define N4_X  (B_*T_*E_/4)
#define N4_WQ (E_*E_/4)
#define N4_WV (E2_*E_/4)
#define F4_0  N4_X
#define F4_1  (F4_0 + N4_WQ)
#define F4_2  (F4_1 + N4_WQ)
#define F4_3  (F4_2 + N4_WV)
#define F4_4  (F4_3 + N4_WV)
#define F4_TOT (F4_4 + N4_WV)

__global__ void f2h_all(const float* __restrict__ x,
                        const float* __restrict__ Wq, const float* __restrict__ Wk,
                        const float* __restrict__ Wv, const float* __restrict__ Wg,
                        const float* __restrict__ Wo)
{
    int i = blockIdx.x * blockDim.x + threadIdx.x;
    if (i >= F4_TOT) return;
    const float* src; __half* dst; int off;
    if (i < F4_0)      { src = x;  dst = g_xh;  off = i; }
    else if (i < F4_1) { src = Wq; dst = g_wqh; off = i - F4_0; }
    else if (i < F4_2) { src = Wk; dst = g_wkh; off = i - F4_1; }
    else if (i < F4_3) { src = Wv; dst = g_wvh; off = i - F4_2; }
    else if (i < F4_4) { src = Wg; dst = g_wgh; off = i - F4_3; }
    else               { src = Wo; dst = g_woh; off = i - F4_4; }
    float4 v = *(const float4*)(src + (size_t)off * 4);
    __half2 h[2];
    h[0] = __floats2half2_rn(v.x, v.y);
    h[1] = __floats2half2_rn(v.z, v.w);
    *(uint2*)(dst + (size_t)off * 4) = *(uint2*)h;
}

// ===== fp16 tensor-core GEMM core: 3-stage pipeline =====
#define BKH 64
#define TILEA 18432
#define STGB  36864
#define GEMMH_SMEM (3*STGB)

template<int ACT>
__device__ __forceinline__ void gemm_h_body(
    const __half* __restrict__ A, const __half* __restrict__ W,
    const float* __restrict__ bias, void* __restrict__ Cout,
    int K, int Ncols, float scale,
    const float* __restrict__ sn, const float* __restrict__ cs, char* smh)
{
    const int tid = threadIdx.x;
    const int wid = tid >> 5, lane = tid & 31;
    const int wm = wid & 1, wn = wid >> 1;
    const int g = lane >> 2, q = lane & 3;
    const int bx = blockIdx.x, by = blockIdx.y;

    const __half* Ab = A + (size_t)(by * 128) * K;
    const __half* Wb = W + (size_t)(bx * 128) * K;
    const uint32_t sb = smem_u32(smh);

    const int lr  = tid >> 1;
    const int lcu = (tid & 1) * 4;
    const int lrow8 = (lane & 7) + ((lane >> 3) & 1) * 8;
    const int koffB = (lane >> 4) * 16;
    const uint32_t ldoff = (uint32_t)(lr * 144 + lcu * 16);

    float acc[4][4][4] = {};
    const int NS = K / BKH;

    #pragma unroll
    for (int s = 0; s < 2; s++) {
        const uint32_t stg = sb + (uint32_t)s * STGB;
        const __half* As = Ab + (size_t)lr * K + s * BKH + lcu * 8;
        const __half* Ws = Wb + (size_t)lr * K + s * BKH + lcu * 8;
        #pragma unroll
        for (int i = 0; i < 4; i++) {
            cp16(stg + ldoff + i * 16, As + i * 8);
            cp16(stg + TILEA + ldoff + i * 16, Ws + i * 8);
        }
        cp_commit();
    }

    for (int s = 0; s < NS; s++) {
        asm volatile("cp.async.wait_group 1;");
        __syncthreads();
        if (s + 2 < NS) {
            const uint32_t stg = sb + (uint32_t)((s + 2) % 3) * STGB;
            const __half* As = Ab + (size_t)lr * K + (s + 2) * BKH + lcu * 8;
            const __half* Ws = Wb + (size_t)lr * K + (s + 2) * BKH + lcu * 8;
            #pragma unroll
            for (int i = 0; i < 4; i++) {
                cp16(stg + ldoff + i * 16, As + i * 8);
                cp16(stg + TILEA + ldoff + i * 16, Ws + i * 8);
            }
        }
        cp_commit();

        const uint32_t stg = sb + (uint32_t)(s % 3) * STGB;
        const uint32_t a_base = stg + (uint32_t)((wm * 64 + lrow8) * 144 + koffB);
        const uint32_t b_base = stg + TILEA + (uint32_t)((wn * 32 + lrow8) * 144 + koffB);
        #pragma unroll
        for (int ks = 0; ks < 4; ks++) {
            const uint32_t kc2 = ks * 32;
            uint32_t af[4][4];
            #pragma unroll
            for (int mf = 0; mf < 4; mf++) ldm_x4(af[mf], a_base + mf * 16 * 144 + kc2);
            uint32_t bf[4][2];
            #pragma unroll
            for (int nf2 = 0; nf2 < 2; nf2++) {
                uint32_t t4[4];
                ldm_x4(t4, b_base + nf2 * 16 * 144 + kc2);
                unpack_b(t4, bf[2*nf2], bf[2*nf2+1]);
            }
            #pragma unroll
            for (int mf = 0; mf < 4; mf++)
                #pragma unroll
                for (int nf = 0; nf < 4; nf++)
                    mma_f16(acc[mf][nf], af[mf], bf[nf]);
        }
    }

    #pragma unroll
    for (int mf = 0; mf < 4; mf++) {
        #pragma unroll
        for (int nf = 0; nf < 4; nf++) {
            const int row = by * 128 + wm * 64 + mf * 16 + g;
            const int col = bx * 128 + wn * 32 + nf * 8 + q * 2;
            const float b0 = bias[col], b1 = bias[col + 1];
            float o00 = (acc[mf][nf][0] + b0) * scale;
            float o01 = (acc[mf][nf][1] + b1) * scale;
            float o10 = (acc[mf][nf][2] + b0) * scale;
            float o11 = (acc[mf][nf][3] + b1) * scale;
            if (ACT == 2) {
                const int d = col & (KD_ - 1);
                const int t0 = row & (T_ - 1);
                const int t1 = t0 + 8;
                float c0 = cs[t0*KD_ + d], c1 = cs[t0*KD_ + d + 1];
                float s0 = sn[t0*KD_ + d], s1 = sn[t0*KD_ + d + 1];
                float r0 = o00 * c0 - o01 * s0;
                float r1 = o01 * c1 + o00 * s1;
                o00 = r0; o01 = r1;
                c0 = cs[t1*KD_ + d]; c1 = cs[t1*KD_ + d + 1];
                s0 = sn[t1*KD_ + d]; s1 = sn[t1*KD_ + d + 1];
                r0 = o10 * c0 - o11 * s0;
                r1 = o11 * c1 + o10 * s1;
                o10 = r0; o11 = r1;
            }
            if (ACT == 1) {
                __half* C = (__half*)Cout;
                float s00 = o00 / (1.f + expf(-o00));
                float s01 = o01 / (1.f + expf(-o01));
                float s10 = o10 / (1.f + expf(-o10));
                float s11 = o11 / (1.f + expf(-o11));
                __half2 h0 = __floats2half2_rn(s00, s01);
                __half2 h1 = __floats2half2_rn(s10, s11);
                *(uint32_t*)(C + (size_t)row * Ncols + col) = *(uint32_t*)&h0;
                *(uint32_t*)(C + (size_t)(row + 8) * Ncols + col) = *(uint32_t*)&h1;
            } else {
                float* C = (float*)Cout;
                *(float2*)(C + (size_t)row * Ncols + col) = make_float2(o00, o01);
                *(float2*)(C + (size_t)(row + 8) * Ncols + col) = make_float2(o10, o11);
            }
        }
    }
}

__global__ void __launch_bounds__(256)
gemm_qk(const __half* __restrict__ A,
        const __half* __restrict__ Wq, const float* __restrict__ bq,
        const __half* __restrict__ Wk, const float* __restrict__ bk,
        float kscale,
        const float* __restrict__ sn, const float* __restrict__ cs)
{
    extern __shared__ __align__(128) char smh[];
    if (blockIdx.z == 0)
        gemm_h_body<2>(A, Wq, bq, g_q, E_, E_, 1.f, sn, cs, smh);
    else
        gemm_h_body<2>(A, Wk, bk, g_k, E_, E_, kscale, sn, cs, smh);
}

__global__ void __launch_bounds__(256)
gemm_vg(const __half* __restrict__ A,
        const __half* __restrict__ Wv, const float* __restrict__ bv,
        const __half* __restrict__ Wg, const float* __restrict__ bg)
{
    extern __shared__ __align__(128) char smh[];
    if (blockIdx.z == 0)
        gemm_h_body<0>(A, Wv, bv, g_v, E_, E2_, 1.f, nullptr, nullptr, smh);
    else
        gemm_h_body<1>(A, Wg, bg, g_gth, E_, E2_, 1.f, nullptr, nullptr, smh);
}

__global__ void __launch_bounds__(256)
gemm_h(const __half* __restrict__ A, const __half* __restrict__ W,
       const float* __restrict__ bias, float* __restrict__ C,
       int K, int Ncols, float scale)
{
    extern __shared__ __align__(128) char smh[];
    gemm_h_body<0>(A, W, bias, C, K, Ncols, scale, nullptr, nullptr, smh);
}

// ===== fused qk -> mask -> isc -> inner (plain fp16 both phases) =====
#define P1   272
#define AQH_ 0
#define BKHo 34816
#define PQ   528
#define QKHo 0
#define PV   144
#define VHo  67584
#define ISCP 104448
#define ISCS 106496
#define QKI_SMEM 107008

__global__ void __launch_bounds__(256, 1)
qki_kernel(const float* __restrict__ mask)
{
    extern __shared__ __align__(128) char sm[];
    const uint32_t sb = smem_u32(sm);
    const int tid = threadIdx.x;
    const int wid = tid >> 5, lane = tid & 31;
    const int wm = wid & 1, wn = wid >> 1;
    const int g = lane >> 2, q = lane & 3;
    const int z = blockIdx.x, chunk = z >> 1, hf = z & 1;
    const int b = chunk / (NC_*H_);
    const int n = (chunk / H_) % NC_;
    const int h = chunk % H_;
    const int row0 = hf * 128;

    const int lrow8 = (lane & 7) + ((lane >> 3) & 1) * 8;
    const int koffB = (lane >> 4) * 16;

    const float* qsrc = g_q + ((size_t)(b*T_ + n*CH_ + row0)) * E_ + h*KD_;
    const float* ksrc = g_k + ((size_t)(b*T_ + n*CH_)) * E_ + h*KD_;
    {
        const int r_ = tid >> 4, c_ = (tid & 15) * 8;
        #pragma unroll
        for (int p = 0; p < 8; p++) {
            int r = p * 16 + r_;
            float4 u0 = *(const float4*)(qsrc + (size_t)r * E_ + c_);
            float4 u1 = *(const float4*)(qsrc + (size_t)r * E_ + c_ + 4);
            uint4 hi;
            hi.x = rnpack(u0.x, u0.y); hi.y = rnpack(u0.z, u0.w);
            hi.z = rnpack(u1.x, u1.y); hi.w = rnpack(u1.z, u1.w);
            *(uint4*)(sm + AQH_ + r * P1 + c_ * 2) = hi;
        }
        #pragma unroll
        for (int p = 0; p < 16; p++) {
            int r = p * 16 + r_;
            float4 u0 = *(const float4*)(ksrc + (size_t)r * E_ + c_);
            float4 u1 = *(const float4*)(ksrc + (size_t)r * E_ + c_ + 4);
            uint4 hi;
            hi.x = rnpack(u0.x, u0.y); hi.y = rnpack(u0.z, u0.w);
            hi.z = rnpack(u1.x, u1.y); hi.w = rnpack(u1.z, u1.w);
            *(uint4*)(sm + BKHo + r * P1 + c_ * 2) = hi;
        }
    }
    __syncthreads();

    float acc[4][8][4] = {};

    // ---- phase 1: qk, plain fp16 ----
    {
        const uint32_t aH = sb + AQH_ + (uint32_t)((wm*64 + lrow8) * P1 + koffB);
        const uint32_t bH = sb + BKHo + (uint32_t)((wn*64 + lrow8) * P1 + koffB);
        #pragma unroll
        for (int ks = 0; ks < 8; ks++) {
            const uint32_t kb = ks * 32;
            uint32_t af[4][4];
            #pragma unroll
            for (int mf = 0; mf < 4; mf++) ldm_x4(af[mf], aH + mf * 16 * P1 + kb);
            uint32_t bf[8][2];
            #pragma unroll
            for (int nf2 = 0; nf2 < 4; nf2++) {
                uint32_t t4[4];
                ldm_x4(t4, bH + nf2 * 16 * P1 + kb);
                unpack_b(t4, bf[2*nf2], bf[2*nf2+1]);
            }
            #pragma unroll
            for (int mf = 0; mf < 4; mf++)
                #pragma unroll
                for (int nf = 0; nf < 8; nf++)
                    mma_f16(acc[mf][nf], af[mf], bf[nf]);
        }
    }
    __syncthreads();

    {
        float psl[4] = {0,0,0,0}, psh[4] = {0,0,0,0};
        const float* mbase = mask + (size_t)h * (CH_*CH_) + (size_t)row0 * CH_;
        #pragma unroll
        for (int mf = 0; mf < 4; mf++) {
            const int r0 = wm*64 + mf*16 + g, r1 = r0 + 8;
            const float* m0 = mbase + (size_t)r0 * CH_;
            const float* m1 = mbase + (size_t)r1 * CH_;
            #pragma unroll
            for (int nf = 0; nf < 8; nf++) {
                const int c0 = wn*64 + nf*8 + q*2;
                float v00 = acc[mf][nf][0] * m0[c0];
                float v01 = acc[mf][nf][1] * m0[c0+1];
                float v10 = acc[mf][nf][2] * m1[c0];
                float v11 = acc[mf][nf][3] * m1[c0+1];
                psl[mf] += fabsf(v00) + fabsf(v01);
                psh[mf] += fabsf(v10) + fabsf(v11);
                *(uint32_t*)(sm + QKHo + r0 * PQ + c0 * 2) = rnpack(v00, v01);
                *(uint32_t*)(sm + QKHo + r1 * PQ + c0 * 2) = rnpack(v10, v11);
            }
        }
        float* iscp = (float*)(sm + ISCP);
        #pragma unroll
        for (int mf = 0; mf < 4; mf++) {
            float pl = psl[mf], ph = psh[mf];
            pl += __shfl_xor_sync(0xffffffffu, pl, 1);
            pl += __shfl_xor_sync(0xffffffffu, pl, 2);
            ph += __shfl_xor_sync(0xffffffffu, ph, 1);
            ph += __shfl_xor_sync(0xffffffffu, ph, 2);
            if (q == 0) {
                iscp[(wm*64 + mf*16 + g) * 4 + wn] = pl;
                iscp[(wm*64 + mf*16 + g + 8) * 4 + wn] = ph;
            }
        }
    }
    __syncthreads();
    if (tid < 128) {
        const float* ip = (const float*)(sm + ISCP) + tid * 4;
        float s = ip[0] + ip[1] + ip[2] + ip[3];
        g_isc[chunk*CH_ + row0 + tid] = s;
        ((float*)(sm + ISCS))[tid] = fmaxf(s, 1.f);
    }

    #pragma unroll
    for (int mf = 0; mf < 4; mf++)
        #pragma unroll
        for (int nf = 0; nf < 8; nf++)
            #pragma unroll
            for (int e = 0; e < 4; e++) acc[mf][nf][e] = 0.f;

    const float* vsrc = g_v + ((size_t)(b*T_ + n*CH_)) * E2_ + h*HD_;
    for (int sl = 0; sl < 4; sl++) {
        __syncthreads();
        {
            const int d2 = (tid >> 6) << 1;
            const int c_ = (tid & 63) * 4;
            #pragma unroll
            for (int p = 0; p < 8; p++) {
                int dl = p * 8 + d2;
                int d = sl * 64 + dl;
                float4 ua = *(const float4*)(vsrc + (size_t)d * E2_ + c_);
                float4 ub = *(const float4*)(vsrc + (size_t)(d + 1) * E2_ + c_);
                const float fa[4] = {ua.x, ua.y, ua.z, ua.w};
                const float fb[4] = {ub.x, ub.y, ub.z, ub.w};
                #pragma unroll
                for (int j = 0; j < 4; j++)
                    *(uint32_t*)(sm + VHo + (c_ + j) * PV + dl * 2) = rnpack(fa[j], fb[j]);
            }
        }
        __syncthreads();
        const uint32_t aH = sb + QKHo + (uint32_t)((wm*64 + lrow8) * PQ + sl * 128 + koffB);
        const uint32_t bH = sb + VHo + (uint32_t)((wn*64 + lrow8) * PV + koffB);
        #pragma unroll
        for (int ks = 0; ks < 4; ks++) {
            const uint32_t kb = ks * 32;
            uint32_t af[4][4];
            #pragma unroll
            for (int mf = 0; mf < 4; mf++) ldm_x4(af[mf], aH + mf * 16 * PQ + kb);
            uint32_t bf[8][2];
            #pragma unroll
            for (int nf2 = 0; nf2 < 4; nf2++) {
                uint32_t t4[4];
                ldm_x4(t4, bH + nf2 * 16 * PV + kb);
                unpack_b(t4, bf[2*nf2], bf[2*nf2+1]);
            }
            #pragma unroll
            for (int mf = 0; mf < 4; mf++)
                #pragma unroll
                for (int nf = 0; nf < 8; nf++)
                    mma_f16(acc[mf][nf], af[mf], bf[nf]);
        }
    }

    {
        const float* iscs = (const float*)(sm + ISCS);
        __half* op = g_innerh + (size_t)chunk * (CH_*HD_) + (size_t)row0 * HD_;
        #pragma unroll
        for (int mf = 0; mf < 4; mf++) {
            const int r0 = wm*64 + mf*16 + g, r1 = r0 + 8;
            const float inv0 = 1.f / iscs[r0];
            const float inv1 = 1.f / iscs[r1];
            #pragma unroll
            for (int nf = 0; nf < 8; nf++) {
                const int c0 = wn*64 + nf*8 + q*2;
                *(uint32_t*)(op + (size_t)r0 * HD_ + c0) = rnpack(acc[mf][nf][0] * inv0, acc[mf][nf][1] * inv0);
                *(uint32_t*)(op + (size_t)r1 * HD_ + c0) = rnpack(acc[mf][nf][2] * inv1, acc[mf][nf][3] * inv1);
            }
        }
    }
}

// ===== kv = (w*k)^T @ v  (plain fp16) =====
#define KT_H 0
#define KVT_H 18432
#define KV_SMEM 55296

__global__ void __launch_bounds__(256, 1)
kv_mma(const float* __restrict__ mask)
{
    extern __shared__ __align__(128) char sm[];
    const uint32_t sb = smem_u32(sm);
    const int tid = threadIdx.x;
    const int wid = tid >> 5, lane = tid & 31;
    const int wm = wid & 1, wn = wid >> 1;
    const int g = lane >> 2, q = lane & 3;
    const int chunk = blockIdx.x;
    const int b = chunk / (NC_*H_);
    const int n = (chunk / H_) % NC_;
    const int h = chunk % H_;
    const int lrow8 = (lane & 7) + ((lane >> 3) & 1) * 8;
    const int koffB = (lane >> 4) * 16;

    const float* ksrc = g_k + ((size_t)(b*T_ + n*CH_)) * E_ + h*KD_;
    const float* vsrc = g_v + ((size_t)(b*T_ + n*CH_)) * E2_ + h*HD_;
    const float* wrow = mask + (size_t)h * (CH_*CH_) + (size_t)(CH_-1) * CH_;

    float acc[4][8][4] = {};

    for (int sl = 0; sl < 4; sl++) {
        __syncthreads();
        {
            const int cp = (tid >> 3) << 1;
            const int kb_ = (tid & 7) * 16;
            const int c = sl * 64 + cp;
            const float w0 = wrow[c], w1 = wrow[c + 1];
            const float* s0 = ksrc + (size_t)c * E_;
            const float* s1 = ksrc + (size_t)(c + 1) * E_;
            #pragma unroll
            for (int p = 0; p < 4; p++) {
                const int kd = kb_ + p * 4;
                float4 u0 = *(const float4*)(s0 + kd);
                float4 u1 = *(const float4*)(s1 + kd);
                const float f0[4] = {u0.x * w0, u0.y * w0, u0.z * w0, u0.w * w0};
                const float f1[4] = {u1.x * w1, u1.y * w1, u1.z * w1, u1.w * w1};
                #pragma unroll
                for (int j = 0; j < 4; j++)
                    *(uint32_t*)(sm + KT_H + (kd + j) * 144 + cp * 2) = rnpack(f0[j], f1[j]);
            }
        }
        {
            const int d2 = (tid >> 6) << 1;
            const int c_ = (tid & 63) * 4;
            #pragma unroll
            for (int p = 0; p < 8; p++) {
                int dl = p * 8 + d2;
                int c = sl * 64 + dl;
                float4 ua = *(const float4*)(vsrc + (size_t)c * E2_ + c_);
                float4 ub = *(const float4*)(vsrc + (size_t)(c + 1) * E2_ + c_);
                const float fa[4] = {ua.x, ua.y, ua.z, ua.w};
                const float fb[4] = {ub.x, ub.y, ub.z, ub.w};
                #pragma unroll
                for (int j = 0; j < 4; j++)
                    *(uint32_t*)(sm + KVT_H + (c_ + j) * 144 + dl * 2) = rnpack(fa[j], fb[j]);
            }
        }
        __syncthreads();
        const uint32_t aH = sb + KT_H + (uint32_t)((wm*64 + lrow8) * 144 + koffB);
        const uint32_t bH = sb + KVT_H + (uint32_t)((wn*64 + lrow8) * 144 + koffB);
        #pragma unroll
        for (int ks = 0; ks < 4; ks++) {
            const uint32_t kb = ks * 32;
            uint32_t af[4][4];
            #pragma unroll
            for (int mf = 0; mf < 4; mf++) ldm_x4(af[mf], aH + mf * 16 * 144 + kb);
            uint32_t bf[8][2];
            #pragma unroll
            for (int nf2 = 0; nf2 < 4; nf2++) {
                uint32_t t4[4];
                ldm_x4(t4, bH + nf2 * 16 * 144 + kb);
                unpack_b(t4, bf[2*nf2], bf[2*nf2+1]);
            }
            #pragma unroll
            for (int mf = 0; mf < 4; mf++)
                #pragma unroll
                for (int nf = 0; nf < 8; nf++)
                    mma_f16(acc[mf][nf], af[mf], bf[nf]);
        }
    }

    float* op = g_kv + (size_t)chunk * (KD_*HD_);
    #pragma unroll
    for (int mf = 0; mf < 4; mf++) {
        const int r0 = wm*64 + mf*16 + g, r1 = r0 + 8;
        #pragma unroll
        for (int nf = 0; nf < 8; nf++) {
            const int c0 = wn*64 + nf*8 + q*2;
            *(float2*)(op + (size_t)r0 * HD_ + c0) = make_float2(acc[mf][nf][0], acc[mf][nf][1]);
            *(float2*)(op + (size_t)r1 * HD_ + c0) = make_float2(acc[mf][nf][2], acc[mf][nf][3]);
        }
    }
}

// ---------------- cross-chunk scan ----------------
__global__ __launch_bounds__(256)
void scan_kernel(const float* __restrict__ cdec)
{
    const int vb = blockIdx.x & 15;
    const int bh = blockIdx.x >> 4;
    const int b = bh / H_, h = bh % H_;
    const int v0 = vb * 16;
    const int tid = threadIdx.x;
    const int v = tid & 15;
    const int kg = tid >> 4;
    float s[8] = {0,0,0,0,0,0,0,0};
    __shared__ float sc[16];
    __shared__ float red[256];
    if (tid < 16) sc[tid] = 1.f;
    __syncthreads();
    const float cd = cdec[h];
    for (int n = 0; n < NC_; n++) {
        const int chunk = (b*NC_ + n)*H_ + h;
        const size_t zo = (size_t)chunk * (KD_*HD_);
        float invsc = 1.f / sc[v];
        #pragma unroll
        for (int i = 0; i < 8; i++)
            g_kvr[zo + (size_t)(kg*8+i)*HD_ + v0 + v] = s[i] * invsc;
        if (tid < 16) g_csc[chunk*HD_ + v0 + tid] = sc[tid];
        float p = 0.f;
        #pragma unroll
        for (int i = 0; i < 8; i++) {
            s[i] = s[i]*cd + g_kv[zo + (size_t)(kg*8+i)*HD_ + v0 + v];
            p += fabsf(s[i]);
        }
        red[tid] = p;
        __syncthreads();
        if (tid < 16) {
            float sum = 0.f;
            #pragma unroll
            for (int j = 0; j < 16; j++) sum += red[j*16 + tid];
            sc[tid] = fmaxf(sum, 1.f);
        }
        __syncthreads();
    }
}

// ===== cross = (qr*idec) @ kv_rec + combine + LN + silu gate (split, merged) =====
#define CA_H  0
#define CA_L  34816
#define CB_H  69632
#define CB_L  106496
#define CPART 143360
#define CRCSC 147456
#define CRISC 148480
#define CROSS_SMEM 148992

__global__ void __launch_bounds__(256, 1)
cross_mma(const float* __restrict__ idec)
{
    extern __shared__ __align__(128) char sm[];
    const uint32_t sb = smem_u32(sm);
    const int tid = threadIdx.x;
    const int wid = tid >> 5, lane = tid & 31;
    const int wm = wid & 1, wn = wid >> 1;
    const int g = lane >> 2, q = lane & 3;
    const int z = blockIdx.x, chunk = z >> 1, hf = z & 1;
    const int b = chunk / (NC_*H_);
    const int n = (chunk / H_) % NC_;
    const int h = chunk % H_;
    const int row0 = hf * 128;
    const int lrow8 = (lane & 7) + ((lane >> 3) & 1) * 8;
    const int koffB = (lane >> 4) * 16;

    {
        float c = g_csc[chunk*HD_ + tid];
        ((float*)(sm + CRCSC))[tid] = 1.f / c;
        if (tid < 128) {
            float s = g_isc[chunk*CH_ + row0 + tid];
            ((float*)(sm + CRISC))[tid] = 1.f / fmaxf(s, 1.f);
        }
    }
    {
        const float* qsrc = g_q + ((size_t)(b*T_ + n*CH_ + row0)) * E_ + h*KD_;
        const int r_ = tid >> 4, c_ = (tid & 15) * 8;
        #pragma unroll
        for (int p = 0; p < 8; p++) {
            int r = p * 16 + r_;
            float aw = idec[h*CH_ + row0 + r];
            float4 u0 = *(const float4*)(qsrc + (size_t)r * E_ + c_);
            float4 u1 = *(const float4*)(qsrc + (size_t)r * E_ + c_ + 4);
            u0.x *= aw; u0.y *= aw; u0.z *= aw; u0.w *= aw;
            u1.x *= aw; u1.y *= aw; u1.z *= aw; u1.w *= aw;
            uint4 hi, lo;
            split2(u0.x, u0.y, hi.x, lo.x);
            split2(u0.z, u0.w, hi.y, lo.y);
            split2(u1.x, u1.y, hi.z, lo.z);
            split2(u1.z, u1.w, hi.w, lo.w);
            *(uint4*)(sm + CA_H + r * 272 + c_ * 2) = hi;
            *(uint4*)(sm + CA_L + r * 272 + c_ * 2) = lo;
        }
    }

    float acc[4][8][4] = {};
    const float* kvrsrc = g_kvr + (size_t)chunk * (KD_*HD_);

    for (int sl = 0; sl < 2; sl++) {
        __syncthreads();
        {
            const int d2 = (tid >> 6) << 1;
            const int c_ = (tid & 63) * 4;
            #pragma unroll
            for (int p = 0; p < 8; p++) {
                int dl = p * 8 + d2;
                int kd = sl * 64 + dl;
                float4 ua = *(const float4*)(kvrsrc + (size_t)kd * HD_ + c_);
                float4 ub = *(const float4*)(kvrsrc + (size_t)(kd + 1) * HD_ + c_);
                const float fa[4] = {ua.x, ua.y, ua.z, ua.w};
                const float fb[4] = {ub.x, ub.y, ub.z, ub.w};
                #pragma unroll
                for (int j = 0; j < 4; j++) {
                    uint32_t hi, lo;
                    split2(fa[j], fb[j], hi, lo);
                    *(uint32_t*)(sm + CB_H + (c_ + j) * 144 + dl * 2) = hi;
                    *(uint32_t*)(sm + CB_L + (c_ + j) * 144 + dl * 2) = lo;
                }
            }
        }
        __syncthreads();
        const uint32_t aH = sb + CA_H + (uint32_t)((wm*64 + lrow8) * 272 + sl * 128 + koffB);
        const uint32_t aL = sb + CA_L + (uint32_t)((wm*64 + lrow8) * 272 + sl * 128 + koffB);
        const uint32_t bH = sb + CB_H + (uint32_t)((wn*64 + lrow8) * 144 + koffB);
        const uint32_t bL = sb + CB_L + (uint32_t)((wn*64 + lrow8) * 144 + koffB);
        #pragma unroll
        for (int ks = 0; ks < 4; ks++) {
            const uint32_t kb = ks * 32;
            uint32_t afH[4][4], afL[4][4];
            #pragma unroll
            for (int mf = 0; mf < 4; mf++) {
                ldm_x4(afH[mf], aH + mf * 16 * 272 + kb);
                ldm_x4(afL[mf], aL + mf * 16 * 272 + kb);
            }
            uint32_t bfH[8][2], bfL[8][2];
            #pragma unroll
            for (int nf2 = 0; nf2 < 4; nf2++) {
                uint32_t t4[4];
                ldm_x4(t4, bH + nf2 * 16 * 144 + kb);
                unpack_b(t4, bfH[2*nf2], bfH[2*nf2+1]);
                ldm_x4(t4, bL + nf2 * 16 * 144 + kb);
                unpack_b(t4, bfL[2*nf2], bfL[2*nf2+1]);
            }
            #pragma unroll
            for (int mf = 0; mf < 4; mf++)
                #pragma unroll
                for (int nf = 0; nf < 8; nf++) {
                    mma_f16(acc[mf][nf], afH[mf], bfH[nf]);
                    mma_f16(acc[mf][nf], afH[mf], bfL[nf]);
                    mma_f16(acc[mf][nf], afL[mf], bfH[nf]);
                }
        }
    }

    const __half* innp = g_innerh + (size_t)chunk * (CH_*HD_) + (size_t)row0 * HD_;
    const float* rcsc = (const float*)(sm + CRCSC);
    const float* risc = (const float*)(sm + CRISC);
    float* part = (float*)(sm + CPART);

    #pragma unroll
    for (int mf = 0; mf < 4; mf++) {
        const int r0 = wm*64 + mf*16 + g, r1 = r0 + 8;
        const float i0 = risc[r0], i1 = risc[r1];
        float s0 = 0.f, q0 = 0.f, s1 = 0.f, q1 = 0.f;
        #pragma unroll
        for (int nf = 0; nf < 8; nf++) {
            const int c0 = wn*64 + nf*8 + q*2;
            const float rc0 = rcsc[c0], rc1 = rcsc[c0+1];
            float2 in0 = __half22float2(*(const __half2*)(innp + (size_t)r0 * HD_ + c0));
            float2 in1 = __half22float2(*(const __half2*)(innp + (size_t)r1 * HD_ + c0));
            float o00 = in0.x * rc0 + acc[mf][nf][0] * i0;
            float o01 = in0.y * rc1 + acc[mf][nf][1] * i0;
            float o10 = in1.x * rc0 + acc[mf][nf][2] * i1;
            float o11 = in1.y * rc1 + acc[mf][nf][3] * i1;
            acc[mf][nf][0] = o00; acc[mf][nf][1] = o01;
            acc[mf][nf][2] = o10; acc[mf][nf][3] = o11;
            s0 += o00 + o01; q0 += o00*o00 + o01*o01;
            s1 += o10 + o11; q1 += o10*o10 + o11*o11;
        }
        s0 += __shfl_xor_sync(0xffffffffu, s0, 1); s0 += __shfl_xor_sync(0xffffffffu, s0, 2);
        q0 += __shfl_xor_sync(0xffffffffu, q0, 1); q0 += __shfl_xor_sync(0xffffffffu, q0, 2);
        s1 += __shfl_xor_sync(0xffffffffu, s1, 1); s1 += __shfl_xor_sync(0xffffffffu, s1, 2);
        q1 += __shfl_xor_sync(0xffffffffu, q1, 1); q1 += __shfl_xor_sync(0xffffffffu, q1, 2);
        if (q == 0) {
            part[(r0*4 + wn)*2    ] = s0;
            part[(r0*4 + wn)*2 + 1] = q0;
            part[(r1*4 + wn)*2    ] = s1;
            part[(r1*4 + wn)*2 + 1] = q1;
        }
    }
    __syncthreads();

    const __half* gp = g_gth + ((size_t)(b*T_ + n*CH_ + row0)) * E2_ + h*HD_;
    __half* rop      = g_roh + ((size_t)(b*T_ + n*CH_ + row0)) * E2_ + h*HD_;
    #pragma unroll
    for (int mf = 0; mf < 4; mf++) {
        const int r0 = wm*64 + mf*16 + g, r1 = r0 + 8;
        float rs0 = part[(r0*4+0)*2] + part[(r0*4+1)*2] + part[(r0*4+2)*2] + part[(r0*4+3)*2];
        float rq0 = part[(r0*4+0)*2+1] + part[(r0*4+1)*2+1] + part[(r0*4+2)*2+1] + part[(r0*4+3)*2+1];
        float rs1 = part[(r1*4+0)*2] + part[(r1*4+1)*2] + part[(r1*4+2)*2] + part[(r1*4+3)*2];
        float rq1 = part[(r1*4+0)*2+1] + part[(r1*4+1)*2+1] + part[(r1*4+2)*2+1] + part[(r1*4+3)*2+1];
        const float mean0 = rs0 * (1.f/HD_);
        const float mean1 = rs1 * (1.f/HD_);
        const float rstd0 = rsqrtf(rq0 * (1.f/HD_) - mean0*mean0 + 1e-5f);
        const float rstd1 = rsqrtf(rq1 * (1.f/HD_) - mean1*mean1 + 1e-5f);
        #pragma unroll
        for (int nf = 0; nf < 8; nf++) {
            const int c0 = wn*64 + nf*8 + q*2;
            float2 gs0 = __half22float2(*(const __half2*)(gp + (size_t)r0 * E2_ + c0));
            float2 gs1 = __half22float2(*(const __half2*)(gp + (size_t)r1 * E2_ + c0));
            float o00 = gs0.x * (acc[mf][nf][0] - mean0) * rstd0;
            float o01 = gs0.y * (acc[mf][nf][1] - mean0) * rstd0;
            float o10 = gs1.x * (acc[mf][nf][2] - mean1) * rstd1;
            float o11 = gs1.y * (acc[mf][nf][3] - mean1) * rstd1;
            __half2 h0 = __floats2half2_rn(o00, o01);
            __half2 h1 = __floats2half2_rn(o10, o11);
            *(uint32_t*)(rop + (size_t)r0 * E2_ + c0) = *(uint32_t*)&h0;
            *(uint32_t*)(rop + (size_t)r1 * E2_ + c0) = *(uint32_t*)&h1;
        }
    }
}

// ================= launch =================
extern "C" void kernel_launch(void* const* d_in, const int* in_sizes, int n_in,
                              void* d_out, int out_size)
{
    const float* x    = (const float*)d_in[0];
    const float* sn   = (const float*)d_in[1];
    const float* cs   = (const float*)d_in[2];
    const float* mask = (const float*)d_in[3];
    const float* cdec = (const float*)d_in[4];
    const float* idec = (const float*)d_in[5];
    const float* Wq = (const float*)d_in[6];
    const float* bq = (const float*)d_in[7];
    const float* Wk = (const float*)d_in[8];
    const float* bk = (const float*)d_in[9];
    const float* Wv = (const float*)d_in[10];
    const float* bv = (const float*)d_in[11];
    const float* Wg = (const float*)d_in[12];
    const float* bg = (const float*)d_in[13];
    const float* Wo = (const float*)d_in[14];
    const float* bo = (const float*)d_in[15];
    float* out = (float*)d_out;

    __half *xh, *roh, *wqh, *wkh, *wvh, *wgh, *woh;
    cudaGetSymbolAddress((void**)&xh,  g_xh);
    cudaGetSymbolAddress((void**)&roh, g_roh);
    cudaGetSymbolAddress((void**)&wqh, g_wqh);
    cudaGetSymbolAddress((void**)&wkh, g_wkh);
    cudaGetSymbolAddress((void**)&wvh, g_wvh);
    cudaGetSymbolAddress((void**)&wgh, g_wgh);
    cudaGetSymbolAddress((void**)&woh, g_woh);

    cudaFuncSetAttribute(gemm_h, cudaFuncAttributeMaxDynamicSharedMemorySize, GEMMH_SMEM);
    cudaFuncSetAttribute(gemm_qk, cudaFuncAttributeMaxDynamicSharedMemorySize, GEMMH_SMEM);
    cudaFuncSetAttribute(gemm_vg, cudaFuncAttributeMaxDynamicSharedMemorySize, GEMMH_SMEM);
    cudaFuncSetAttribute(qki_kernel, cudaFuncAttributeMaxDynamicSharedMemorySize, QKI_SMEM);
    cudaFuncSetAttribute(kv_mma, cudaFuncAttributeMaxDynamicSharedMemorySize, KV_SMEM);
    cudaFuncSetAttribute(cross_mma, cudaFuncAttributeMaxDynamicSharedMemorySize, CROSS_SMEM);

    const int M = B_*T_;
    const float kscale = 1.0f / sqrtf((float)KD_);

    f2h_all<<<(F4_TOT + 255)/256, 256>>>(x, Wq, Wk, Wv, Wg, Wo);

    gemm_qk<<<dim3(E_/128,  M/128, 2), 256, GEMMH_SMEM>>>(xh, wqh, bq, wkh, bk, kscale, sn, cs);
    gemm_vg<<<dim3(E2_/128, M/128, 2), 256, GEMMH_SMEM>>>(xh, wvh, bv, wgh, bg);
    qki_kernel<<<2*NCHUNKS, 256, QKI_SMEM>>>(mask);
    kv_mma    <<<NCHUNKS,   256, KV_SMEM>>>(mask);
    scan_kernel<<<B_*H_*(HD_/16), 256>>>(cdec);
    cross_mma <<<2*NCHUNKS, 256, CROSS_SMEM>>>(idec);
    gemm_h<<<dim3(E_/128, M/128), 256, GEMMH_SMEM>>>(roh, woh, bo, out, E2_, E_, 1.f);
}